// round 1
// baseline (speedup 1.0000x reference)
#include <cuda_runtime.h>
#include <cstdint>

#define B_   4
#define S_   2048
#define DM_  1024
#define H_   16
#define DK_  64

// Scratch (device globals: allocation-free per harness rules)
__device__ float g_Q[B_*H_*S_*DK_];   // [B,H,S,DK]
__device__ float g_K[B_*H_*S_*DK_];
__device__ float g_V[B_*H_*S_*DK_];
__device__ float g_MH[B_*S_*DM_];     // merged heads [B,S,D]

// ---------------------------------------------------------------------------
// C = A (M x 1024) * W^T   with W row-major [N,1024] (K contiguous).
// mode 0: C plain [M,1024] row-major.
// mode 1: C in head-split layout [B,H,S,DK].
// 128x128 block tile, 16-wide K tile, 256 threads, 8x8 per-thread microtile.
// ---------------------------------------------------------------------------
__global__ __launch_bounds__(256) void gemm_abt(const float* __restrict__ A,
                                                const float* __restrict__ W,
                                                float* __restrict__ C,
                                                int mode) {
    __shared__ float As[16][128];
    __shared__ float Bs[16][128];

    const int bm  = blockIdx.y * 128;
    const int bn  = blockIdx.x * 128;
    const int tid = threadIdx.x;
    const int tr  = tid >> 4;          // 0..15
    const int tc  = tid & 15;          // 0..15
    const int lr  = tid >> 2;          // 0..63 (load rows)
    const int lc  = (tid & 3) << 2;    // 0,4,8,12 (load col group)

    float acc[8][8];
#pragma unroll
    for (int i = 0; i < 8; i++)
#pragma unroll
        for (int j = 0; j < 8; j++) acc[i][j] = 0.f;

    for (int k0 = 0; k0 < 1024; k0 += 16) {
#pragma unroll
        for (int g = 0; g < 2; g++) {
            int row = lr + g * 64;
            float4 av = *(const float4*)(A + (size_t)(bm + row) * 1024 + k0 + lc);
            As[lc + 0][row] = av.x; As[lc + 1][row] = av.y;
            As[lc + 2][row] = av.z; As[lc + 3][row] = av.w;
            float4 wv = *(const float4*)(W + (size_t)(bn + row) * 1024 + k0 + lc);
            Bs[lc + 0][row] = wv.x; Bs[lc + 1][row] = wv.y;
            Bs[lc + 2][row] = wv.z; Bs[lc + 3][row] = wv.w;
        }
        __syncthreads();

#pragma unroll
        for (int kk = 0; kk < 16; kk++) {
            float a[8], b[8];
#pragma unroll
            for (int i = 0; i < 4; i++) {
                a[i]     = As[kk][tr * 4 + i];
                a[4 + i] = As[kk][64 + tr * 4 + i];
            }
#pragma unroll
            for (int j = 0; j < 4; j++) {
                b[j]     = Bs[kk][tc * 4 + j];
                b[4 + j] = Bs[kk][64 + tc * 4 + j];
            }
#pragma unroll
            for (int i = 0; i < 8; i++)
#pragma unroll
                for (int j = 0; j < 8; j++) acc[i][j] += a[i] * b[j];
        }
        __syncthreads();
    }

    if (mode == 0) {
#pragma unroll
        for (int i = 0; i < 8; i++) {
            int row = bm + ((i < 4) ? (tr * 4 + i) : (64 + tr * 4 + i - 4));
            float4 v0 = make_float4(acc[i][0], acc[i][1], acc[i][2], acc[i][3]);
            float4 v1 = make_float4(acc[i][4], acc[i][5], acc[i][6], acc[i][7]);
            *(float4*)(C + (size_t)row * 1024 + bn + tc * 4)      = v0;
            *(float4*)(C + (size_t)row * 1024 + bn + 64 + tc * 4) = v1;
        }
    } else {
#pragma unroll
        for (int i = 0; i < 8; i++) {
            int row = bm + ((i < 4) ? (tr * 4 + i) : (64 + tr * 4 + i - 4));
            int bb = row >> 11, ss = row & 2047;
#pragma unroll
            for (int j = 0; j < 8; j++) {
                int col = bn + ((j < 4) ? (tc * 4 + j) : (64 + tc * 4 + j - 4));
                int hh = col >> 6, dk = col & 63;
                C[(((size_t)(bb * 16 + hh)) * 2048 + ss) * 64 + dk] = acc[i][j];
            }
        }
    }
}

// ---------------------------------------------------------------------------
// Flash-attention over head-split Q/K/V, output merged into g_MH [B,S,D].
// Grid: (S/64, H, B). 256 threads. 64x64 score tile, 4x4 reg blocking.
// Thread (tr,tc): rows tr*4+i, cols/keys tc+16*j (interleaved -> no bank
// conflicts with 65-float padded smem rows).
// ---------------------------------------------------------------------------
#define ATTN_SMEM (4 * 64 * 65 * 4 + 64 * 4)

__global__ __launch_bounds__(256) void attn_kernel(const int* __restrict__ mask) {
    extern __shared__ float sm[];
    float* Qs = sm;                  // 64 x 65
    float* Ks = Qs + 64 * 65;        // 64 x 65
    float* Vs = Ks + 64 * 65;        // 64 x 65
    float* Ps = Vs + 64 * 65;        // 64 x 65
    int*   mk = (int*)(Ps + 64 * 65);

    const int b  = blockIdx.z;
    const int h  = blockIdx.y;
    const int q0 = blockIdx.x * 64;
    const int tid = threadIdx.x;
    const int tr = tid >> 4;         // 0..15
    const int tc = tid & 15;         // 0..15
    const float scale = 0.125f;      // 1/sqrt(64)

    const float* Qg = g_Q + (((size_t)b * 16 + h) * 2048 + q0) * 64;
    const float* Kg = g_K + (((size_t)b * 16 + h) * 2048) * 64;
    const float* Vg = g_V + (((size_t)b * 16 + h) * 2048) * 64;

    // Q tile: contiguous 4096 floats
    for (int idx = tid * 4; idx < 4096; idx += 1024) {
        float4 v = *(const float4*)(Qg + idx);
        int rr = idx >> 6, cc = idx & 63;
        float* p = Qs + rr * 65 + cc;
        p[0] = v.x; p[1] = v.y; p[2] = v.z; p[3] = v.w;
    }

    float m_i[4], l_i[4], O[4][4];
#pragma unroll
    for (int i = 0; i < 4; i++) {
        m_i[i] = -1e30f; l_i[i] = 0.f;
#pragma unroll
        for (int j = 0; j < 4; j++) O[i][j] = 0.f;
    }

    for (int j0 = 0; j0 < 2048; j0 += 64) {
        for (int idx = tid * 4; idx < 4096; idx += 1024) {
            int rr = idx >> 6, cc = idx & 63;
            float4 kv = *(const float4*)(Kg + (size_t)j0 * 64 + idx);
            float* pk = Ks + rr * 65 + cc;
            pk[0] = kv.x; pk[1] = kv.y; pk[2] = kv.z; pk[3] = kv.w;
            float4 vv = *(const float4*)(Vg + (size_t)j0 * 64 + idx);
            float* pv = Vs + rr * 65 + cc;
            pv[0] = vv.x; pv[1] = vv.y; pv[2] = vv.z; pv[3] = vv.w;
        }
        if (tid < 64) mk[tid] = mask[b * 2048 + j0 + tid];
        __syncthreads();

        // scores S = Q K^T (rows tr*4+i, keys tc+16*j)
        float s[4][4];
#pragma unroll
        for (int i = 0; i < 4; i++)
#pragma unroll
            for (int j = 0; j < 4; j++) s[i][j] = 0.f;

        for (int d = 0; d < 64; d++) {
            float a[4], bb[4];
#pragma unroll
            for (int i = 0; i < 4; i++) a[i]  = Qs[(tr * 4 + i) * 65 + d];
#pragma unroll
            for (int j = 0; j < 4; j++) bb[j] = Ks[(tc + 16 * j) * 65 + d];
#pragma unroll
            for (int i = 0; i < 4; i++)
#pragma unroll
                for (int j = 0; j < 4; j++) s[i][j] += a[i] * bb[j];
        }

        // scale + mask + local max
        float tmax[4];
#pragma unroll
        for (int i = 0; i < 4; i++) tmax[i] = -1e30f;
#pragma unroll
        for (int j = 0; j < 4; j++) {
            bool mz = (mk[tc + 16 * j] == 0);
#pragma unroll
            for (int i = 0; i < 4; i++) {
                float v = mz ? -1e9f : s[i][j] * scale;
                s[i][j] = v;
                tmax[i] = fmaxf(tmax[i], v);
            }
        }
        // row max across the 16 threads sharing tr (they live in one half-warp)
#pragma unroll
        for (int off = 1; off < 16; off <<= 1)
#pragma unroll
            for (int i = 0; i < 4; i++)
                tmax[i] = fmaxf(tmax[i], __shfl_xor_sync(0xffffffffu, tmax[i], off));

        // online softmax update
        float rs[4];
#pragma unroll
        for (int i = 0; i < 4; i++) {
            float mnew = fmaxf(m_i[i], tmax[i]);
            float corr = __expf(m_i[i] - mnew);
            m_i[i] = mnew;
            l_i[i] *= corr;
#pragma unroll
            for (int j = 0; j < 4; j++) O[i][j] *= corr;
            rs[i] = 0.f;
#pragma unroll
            for (int j = 0; j < 4; j++) {
                float p = __expf(s[i][j] - mnew);
                s[i][j] = p;
                rs[i] += p;
            }
        }
#pragma unroll
        for (int off = 1; off < 16; off <<= 1)
#pragma unroll
            for (int i = 0; i < 4; i++)
                rs[i] += __shfl_xor_sync(0xffffffffu, rs[i], off);
#pragma unroll
        for (int i = 0; i < 4; i++) l_i[i] += rs[i];

        // stash P tile
#pragma unroll
        for (int i = 0; i < 4; i++)
#pragma unroll
            for (int j = 0; j < 4; j++)
                Ps[(tr * 4 + i) * 65 + tc + 16 * j] = s[i][j];
        __syncthreads();

        // O += P V  (rows tr*4+i, dk cols tc+16*j)
        for (int kk = 0; kk < 64; kk++) {
            float a[4], bb[4];
#pragma unroll
            for (int i = 0; i < 4; i++) a[i]  = Ps[(tr * 4 + i) * 65 + kk];
#pragma unroll
            for (int j = 0; j < 4; j++) bb[j] = Vs[kk * 65 + tc + 16 * j];
#pragma unroll
            for (int i = 0; i < 4; i++)
#pragma unroll
                for (int j = 0; j < 4; j++) O[i][j] += a[i] * bb[j];
        }
        __syncthreads();
    }

    // epilogue: O / l, write merged-head layout [B,S,D] at column h*64
    float* out = g_MH + (((size_t)b * 2048 + q0) * 1024) + h * 64;
#pragma unroll
    for (int i = 0; i < 4; i++) {
        float inv = 1.f / l_i[i];
        int row = tr * 4 + i;
#pragma unroll
        for (int j = 0; j < 4; j++)
            out[(size_t)row * 1024 + tc + 16 * j] = O[i][j] * inv;
    }
}

// ---------------------------------------------------------------------------
extern "C" void kernel_launch(void* const* d_in, const int* in_sizes, int n_in,
                              void* d_out, int out_size) {
    const float* q    = (const float*)d_in[0];
    const float* k    = (const float*)d_in[1];
    const float* v    = (const float*)d_in[2];
    const int*   mask = (const int*)  d_in[3];
    const float* Wq   = (const float*)d_in[4];
    const float* Wk   = (const float*)d_in[5];
    const float* Wv   = (const float*)d_in[6];
    const float* Wo   = (const float*)d_in[7];
    float* out = (float*)d_out;

    float *pQ, *pK, *pV, *pMH;
    cudaGetSymbolAddress((void**)&pQ,  g_Q);
    cudaGetSymbolAddress((void**)&pK,  g_K);
    cudaGetSymbolAddress((void**)&pV,  g_V);
    cudaGetSymbolAddress((void**)&pMH, g_MH);

    cudaFuncSetAttribute(attn_kernel,
                         cudaFuncAttributeMaxDynamicSharedMemorySize, ATTN_SMEM);

    dim3 gg(8, 64);     // N/128, M/128
    gemm_abt<<<gg, 256>>>(q, Wq, pQ, 1);
    gemm_abt<<<gg, 256>>>(k, Wk, pK, 1);
    gemm_abt<<<gg, 256>>>(v, Wv, pV, 1);

    dim3 ga(32, 16, 4); // S/64, H, B
    attn_kernel<<<ga, 256, ATTN_SMEM>>>(mask);

    gemm_abt<<<gg, 256>>>(pMH, Wo, out, 0);
}

// round 8
// speedup vs baseline: 1.3053x; 1.3053x over previous
#include <cuda_runtime.h>
#include <cuda_bf16.h>
#include <cstdint>

#define B_   4
#define S_   2048
#define DM_  1024
#define H_   16
#define DK_  64

// ---------------- scratch (device globals; allocation-free) ----------------
__device__ float g_Q[B_*S_*DM_];             // plain [B,S,D] fp32
__device__ float g_K[B_*S_*DM_];
__device__ float g_V[B_*S_*DM_];
__device__ float g_MH[B_*S_*DM_];            // merged heads [B,S,D]
__device__ __nv_bfloat16 g_Ahi[B_*S_*DM_];   // split activations (reused per GEMM)
__device__ __nv_bfloat16 g_Alo[B_*S_*DM_];
__device__ __nv_bfloat16 g_Whi[DM_*DM_];     // split weights (reused per GEMM)
__device__ __nv_bfloat16 g_Wlo[DM_*DM_];

// ---------------- helpers (baseline PTX only: valid at .target sm_103) -----
__device__ __forceinline__ uint32_t smem_u32(const void* p) {
    uint32_t a;
    asm("{ .reg .u64 t; cvta.to.shared.u64 t, %1; cvt.u32.u64 %0, t; }"
        : "=r"(a) : "l"(p));
    return a;
}
__device__ __forceinline__ void ldsm4(uint32_t* r, uint32_t a) {
    asm volatile("ldmatrix.sync.aligned.m8n8.x4.shared.b16 {%0,%1,%2,%3}, [%4];"
                 : "=r"(r[0]), "=r"(r[1]), "=r"(r[2]), "=r"(r[3]) : "r"(a));
}
__device__ __forceinline__ void mma16816(float* d, const uint32_t* a,
                                         const uint32_t* b) {
    asm volatile(
        "mma.sync.aligned.m16n8k16.row.col.f32.bf16.bf16.f32 "
        "{%0,%1,%2,%3}, {%4,%5,%6,%7}, {%8,%9}, {%0,%1,%2,%3};"
        : "+f"(d[0]), "+f"(d[1]), "+f"(d[2]), "+f"(d[3])
        : "r"(a[0]), "r"(a[1]), "r"(a[2]), "r"(a[3]), "r"(b[0]), "r"(b[1]));
}
#define CP16(dst, src) \
    asm volatile("cp.async.cg.shared.global [%0], [%1], 16;" \
                 :: "r"(dst), "l"(src))
#define CPCOMMIT() asm volatile("cp.async.commit_group;" ::: "memory")
#define CPWAIT(n)  asm volatile("cp.async.wait_group %0;" :: "n"(n) : "memory")

// ---------------------------------------------------------------------------
// split fp32 x -> bf16 hi + bf16 lo (x ~= hi + lo, residual ~2^-18 |x|)
// ---------------------------------------------------------------------------
__global__ void split_bf16(const float* __restrict__ x,
                           __nv_bfloat16* __restrict__ hi,
                           __nv_bfloat16* __restrict__ lo, int n) {
    int i = (blockIdx.x * blockDim.x + threadIdx.x) * 4;
    if (i >= n) return;
    float4 v = *(const float4*)(x + i);
    __nv_bfloat16 h0 = __float2bfloat16(v.x);
    __nv_bfloat16 h1 = __float2bfloat16(v.y);
    __nv_bfloat16 h2 = __float2bfloat16(v.z);
    __nv_bfloat16 h3 = __float2bfloat16(v.w);
    __nv_bfloat16 l0 = __float2bfloat16(v.x - __bfloat162float(h0));
    __nv_bfloat16 l1 = __float2bfloat16(v.y - __bfloat162float(h1));
    __nv_bfloat16 l2 = __float2bfloat16(v.z - __bfloat162float(h2));
    __nv_bfloat16 l3 = __float2bfloat16(v.w - __bfloat162float(h3));
    *(__nv_bfloat162*)(hi + i)     = __nv_bfloat162(h0, h1);
    *(__nv_bfloat162*)(hi + i + 2) = __nv_bfloat162(h2, h3);
    *(__nv_bfloat162*)(lo + i)     = __nv_bfloat162(l0, l1);
    *(__nv_bfloat162*)(lo + i + 2) = __nv_bfloat162(l2, l3);
}

// ---------------------------------------------------------------------------
// mma.sync bf16x3 GEMM: C[M,1024] = A[M,1024] * W^T, W row-major [1024,1024].
// D = Ahi*Whi + Ahi*Wlo + Alo*Whi, fp32 accum.
// CTA 128x128, BK=32, 256 threads (8 warps, 4m x 2n, warp tile 32x64).
// cp.async double-buffered. Padded smem rows (stride 40 bf16) for ldmatrix.
// ---------------------------------------------------------------------------
#define BK          32
#define LDSTR       40                       // bf16 elems per smem row
#define MAT_ELEMS   (128 * LDSTR)            // 5120
#define STAGE_ELEMS (4 * MAT_ELEMS)          // 20480
#define GEMM_SMEM   (2 * STAGE_ELEMS * 2)    // 81920 bytes

__global__ __launch_bounds__(256) void gemm_mma(
    const __nv_bfloat16* __restrict__ Ahi, const __nv_bfloat16* __restrict__ Alo,
    const __nv_bfloat16* __restrict__ Bhi, const __nv_bfloat16* __restrict__ Blo,
    float* __restrict__ C) {
    extern __shared__ __nv_bfloat16 smem[];
    const uint32_t sbase = smem_u32(smem);

    const int tid = threadIdx.x;
    const int wid = tid >> 5;
    const int lid = tid & 31;
    const int wm  = wid >> 1;            // 0..3
    const int wn  = wid & 1;             // 0..1
    const int bm  = blockIdx.y * 128;
    const int bn  = blockIdx.x * 128;

    // ---- cp.async load mapping: 4 threads per row, 2 row-groups ----
    const int lrow = tid >> 2;           // 0..63
    const int lseg = tid & 3;            // 16B segment (8 bf16)
    const __nv_bfloat16* gsrc[4];
    gsrc[0] = Ahi + (size_t)(bm + lrow) * 1024 + lseg * 8;
    gsrc[1] = Alo + (size_t)(bm + lrow) * 1024 + lseg * 8;
    gsrc[2] = Bhi + (size_t)(bn + lrow) * 1024 + lseg * 8;
    gsrc[3] = Blo + (size_t)(bn + lrow) * 1024 + lseg * 8;
    const uint32_t sdst = sbase + (uint32_t)(lrow * LDSTR + lseg * 8) * 2;

    // ---- ldmatrix per-lane offsets ----
    // A fragment (m16k16, .x4): row = (l&7)+8*((l>>3)&1), col = (l>>4)*8
    const int ra = ((lid >> 3) & 1) * 8 + (lid & 7);
    const int ca = (lid >> 4) * 8;
    const uint32_t aoff = (uint32_t)((wm * 32 + ra) * LDSTR + ca);
    // B fragment pair (two n8k16 tiles, .x4): row = (l>>4)*8+(l&7), col=((l>>3)&1)*8
    const int rb = (lid >> 4) * 8 + (lid & 7);
    const int cb = ((lid >> 3) & 1) * 8;
    const uint32_t boff = (uint32_t)((wn * 64 + rb) * LDSTR + cb);

    float acc[2][8][4];
#pragma unroll
    for (int t = 0; t < 2; t++)
#pragma unroll
        for (int j = 0; j < 8; j++)
#pragma unroll
            for (int e = 0; e < 4; e++) acc[t][j][e] = 0.f;

    // ---- prologue: prefetch stage 0 ----
#pragma unroll
    for (int m = 0; m < 4; m++)
#pragma unroll
        for (int r2 = 0; r2 < 2; r2++)
            CP16(sdst + (uint32_t)(m * MAT_ELEMS + r2 * 64 * LDSTR) * 2,
                 gsrc[m] + (size_t)r2 * 64 * 1024);
    CPCOMMIT();

    for (int kc = 0; kc < 32; ++kc) {
        __syncthreads();   // guard: compute on the buffer we're about to refill is done
        if (kc < 31) {
            const int k0 = (kc + 1) * BK;
            const uint32_t sb2 = sdst + (uint32_t)(((kc + 1) & 1) * STAGE_ELEMS) * 2;
#pragma unroll
            for (int m = 0; m < 4; m++)
#pragma unroll
                for (int r2 = 0; r2 < 2; r2++)
                    CP16(sb2 + (uint32_t)(m * MAT_ELEMS + r2 * 64 * LDSTR) * 2,
                         gsrc[m] + (size_t)r2 * 64 * 1024 + k0);
            CPCOMMIT();
            CPWAIT(1);
        } else {
            CPWAIT(0);
        }
        __syncthreads();

        const uint32_t mb   = sbase + (uint32_t)((kc & 1) * STAGE_ELEMS) * 2;
        const uint32_t bAhi = mb;
        const uint32_t bAlo = mb + MAT_ELEMS * 2;
        const uint32_t bWhi = mb + 2 * MAT_ELEMS * 2;
        const uint32_t bWlo = mb + 3 * MAT_ELEMS * 2;

#pragma unroll
        for (int k16 = 0; k16 < 2; k16++) {
            const uint32_t kadd = (uint32_t)(k16 * 16) * 2;
            uint32_t ah[2][4], al[2][4], bh[8][2], bl[8][2];
#pragma unroll
            for (int t = 0; t < 2; t++) {
                const uint32_t ao = (aoff + t * 16 * LDSTR) * 2 + kadd;
                ldsm4(ah[t], bAhi + ao);
                ldsm4(al[t], bAlo + ao);
            }
#pragma unroll
            for (int jp = 0; jp < 4; jp++) {
                const uint32_t bo = (boff + jp * 16 * LDSTR) * 2 + kadd;
                uint32_t r[4];
                ldsm4(r, bWhi + bo);
                bh[2*jp][0] = r[0]; bh[2*jp][1] = r[1];
                bh[2*jp+1][0] = r[2]; bh[2*jp+1][1] = r[3];
                ldsm4(r, bWlo + bo);
                bl[2*jp][0] = r[0]; bl[2*jp][1] = r[1];
                bl[2*jp+1][0] = r[2]; bl[2*jp+1][1] = r[3];
            }
#pragma unroll
            for (int t = 0; t < 2; t++)
#pragma unroll
                for (int j = 0; j < 8; j++) {
                    mma16816(acc[t][j], ah[t], bh[j]);
                    mma16816(acc[t][j], ah[t], bl[j]);
                    mma16816(acc[t][j], al[t], bh[j]);
                }
        }
    }

    // ---- epilogue: direct float2 stores ----
    const int r0 = bm + wm * 32 + (lid >> 2);
    const int c0 = bn + wn * 64 + (lid & 3) * 2;
#pragma unroll
    for (int t = 0; t < 2; t++)
#pragma unroll
        for (int j = 0; j < 8; j++) {
            float* p0 = C + (size_t)(r0 + t * 16) * 1024 + c0 + j * 8;
            float* p1 = p0 + 8 * 1024;
            *(float2*)p0 = make_float2(acc[t][j][0], acc[t][j][1]);
            *(float2*)p1 = make_float2(acc[t][j][2], acc[t][j][3]);
        }
}

// ---------------------------------------------------------------------------
// Flash attention over plain-layout Q/K/V [B,S,1024] (head h at col h*64).
// Grid: (S/64, H, B). 256 threads. 64x64 tiles, 4x4 reg blocking. fp32 SIMT.
// ---------------------------------------------------------------------------
#define ATTN_SMEM (4 * 64 * 65 * 4 + 64 * 4)

__global__ __launch_bounds__(256) void attn_kernel(const int* __restrict__ mask) {
    extern __shared__ float sm[];
    float* Qs = sm;                  // 64 x 65
    float* Ks = Qs + 64 * 65;
    float* Vs = Ks + 64 * 65;
    float* Ps = Vs + 64 * 65;
    int*   mk = (int*)(Ps + 64 * 65);

    const int b  = blockIdx.z;
    const int h  = blockIdx.y;
    const int q0 = blockIdx.x * 64;
    const int tid = threadIdx.x;
    const int tr = tid >> 4;
    const int tc = tid & 15;
    const float scale = 0.125f;

    const float* Qg = g_Q + ((size_t)b * 2048 + q0) * 1024 + h * 64;
    const float* Kg = g_K + ((size_t)b * 2048) * 1024 + h * 64;
    const float* Vg = g_V + ((size_t)b * 2048) * 1024 + h * 64;

    for (int idx = tid * 4; idx < 4096; idx += 1024) {
        int rr = idx >> 6, cc = idx & 63;
        float4 v = *(const float4*)(Qg + (size_t)rr * 1024 + cc);
        float* p = Qs + rr * 65 + cc;
        p[0] = v.x; p[1] = v.y; p[2] = v.z; p[3] = v.w;
    }

    float m_i[4], l_i[4], O[4][4];
#pragma unroll
    for (int i = 0; i < 4; i++) {
        m_i[i] = -1e30f; l_i[i] = 0.f;
#pragma unroll
        for (int j = 0; j < 4; j++) O[i][j] = 0.f;
    }

    for (int j0 = 0; j0 < 2048; j0 += 64) {
        for (int idx = tid * 4; idx < 4096; idx += 1024) {
            int rr = idx >> 6, cc = idx & 63;
            float4 kv = *(const float4*)(Kg + (size_t)(j0 + rr) * 1024 + cc);
            float* pk = Ks + rr * 65 + cc;
            pk[0] = kv.x; pk[1] = kv.y; pk[2] = kv.z; pk[3] = kv.w;
            float4 vv = *(const float4*)(Vg + (size_t)(j0 + rr) * 1024 + cc);
            float* pv = Vs + rr * 65 + cc;
            pv[0] = vv.x; pv[1] = vv.y; pv[2] = vv.z; pv[3] = vv.w;
        }
        if (tid < 64) mk[tid] = mask[b * 2048 + j0 + tid];
        __syncthreads();

        float s[4][4];
#pragma unroll
        for (int i = 0; i < 4; i++)
#pragma unroll
            for (int j = 0; j < 4; j++) s[i][j] = 0.f;

        for (int d = 0; d < 64; d++) {
            float a[4], bb[4];
#pragma unroll
            for (int i = 0; i < 4; i++) a[i]  = Qs[(tr * 4 + i) * 65 + d];
#pragma unroll
            for (int j = 0; j < 4; j++) bb[j] = Ks[(tc + 16 * j) * 65 + d];
#pragma unroll
            for (int i = 0; i < 4; i++)
#pragma unroll
                for (int j = 0; j < 4; j++) s[i][j] += a[i] * bb[j];
        }

        float tmax[4];
#pragma unroll
        for (int i = 0; i < 4; i++) tmax[i] = -1e30f;
#pragma unroll
        for (int j = 0; j < 4; j++) {
            bool mz = (mk[tc + 16 * j] == 0);
#pragma unroll
            for (int i = 0; i < 4; i++) {
                float v = mz ? -1e9f : s[i][j] * scale;
                s[i][j] = v;
                tmax[i] = fmaxf(tmax[i], v);
            }
        }
#pragma unroll
        for (int off = 1; off < 16; off <<= 1)
#pragma unroll
            for (int i = 0; i < 4; i++)
                tmax[i] = fmaxf(tmax[i], __shfl_xor_sync(0xffffffffu, tmax[i], off));

        float rs[4];
#pragma unroll
        for (int i = 0; i < 4; i++) {
            float mnew = fmaxf(m_i[i], tmax[i]);
            float corr = __expf(m_i[i] - mnew);
            m_i[i] = mnew;
            l_i[i] *= corr;
#pragma unroll
            for (int j = 0; j < 4; j++) O[i][j] *= corr;
            rs[i] = 0.f;
#pragma unroll
            for (int j = 0; j < 4; j++) {
                float p = __expf(s[i][j] - mnew);
                s[i][j] = p;
                rs[i] += p;
            }
        }
#pragma unroll
        for (int off = 1; off < 16; off <<= 1)
#pragma unroll
            for (int i = 0; i < 4; i++)
                rs[i] += __shfl_xor_sync(0xffffffffu, rs[i], off);
#pragma unroll
        for (int i = 0; i < 4; i++) l_i[i] += rs[i];

#pragma unroll
        for (int i = 0; i < 4; i++)
#pragma unroll
            for (int j = 0; j < 4; j++)
                Ps[(tr * 4 + i) * 65 + tc + 16 * j] = s[i][j];
        __syncthreads();

        for (int kk = 0; kk < 64; kk++) {
            float a[4], bb[4];
#pragma unroll
            for (int i = 0; i < 4; i++) a[i]  = Ps[(tr * 4 + i) * 65 + kk];
#pragma unroll
            for (int j = 0; j < 4; j++) bb[j] = Vs[kk * 65 + tc + 16 * j];
#pragma unroll
            for (int i = 0; i < 4; i++)
#pragma unroll
                for (int j = 0; j < 4; j++) O[i][j] += a[i] * bb[j];
        }
        __syncthreads();
    }

    float* out = g_MH + (((size_t)b * 2048 + q0) * 1024) + h * 64;
#pragma unroll
    for (int i = 0; i < 4; i++) {
        float inv = 1.f / l_i[i];
        int row = tr * 4 + i;
#pragma unroll
        for (int j = 0; j < 4; j++)
            out[(size_t)row * 1024 + tc + 16 * j] = O[i][j] * inv;
    }
}

// ---------------------------------------------------------------------------
extern "C" void kernel_launch(void* const* d_in, const int* in_sizes, int n_in,
                              void* d_out, int out_size) {
    const float* q    = (const float*)d_in[0];
    const float* k    = (const float*)d_in[1];
    const float* v    = (const float*)d_in[2];
    const int*   mask = (const int*)  d_in[3];
    const float* Wq   = (const float*)d_in[4];
    const float* Wk   = (const float*)d_in[5];
    const float* Wv   = (const float*)d_in[6];
    const float* Wo   = (const float*)d_in[7];
    float* out = (float*)d_out;

    float *pQ, *pK, *pV, *pMH;
    __nv_bfloat16 *pAhi, *pAlo, *pWhi, *pWlo;
    cudaGetSymbolAddress((void**)&pQ,   g_Q);
    cudaGetSymbolAddress((void**)&pK,   g_K);
    cudaGetSymbolAddress((void**)&pV,   g_V);
    cudaGetSymbolAddress((void**)&pMH,  g_MH);
    cudaGetSymbolAddress((void**)&pAhi, g_Ahi);
    cudaGetSymbolAddress((void**)&pAlo, g_Alo);
    cudaGetSymbolAddress((void**)&pWhi, g_Whi);
    cudaGetSymbolAddress((void**)&pWlo, g_Wlo);

    cudaFuncSetAttribute(attn_kernel,
                         cudaFuncAttributeMaxDynamicSharedMemorySize, ATTN_SMEM);
    cudaFuncSetAttribute(gemm_mma,
                         cudaFuncAttributeMaxDynamicSharedMemorySize, GEMM_SMEM);

    const int nA = B_ * S_ * DM_;   // 8,388,608
    const int nW = DM_ * DM_;       // 1,048,576
    dim3 csA((nA / 4 + 255) / 256), cb(256);
    dim3 csW((nW / 4 + 255) / 256);
    dim3 gg(8, 64);                 // N/128, M/128
    dim3 ga(32, 16, 4);             // S/64, H, B

    // Q projection
    split_bf16<<<csA, cb>>>(q,  pAhi, pAlo, nA);
    split_bf16<<<csW, cb>>>(Wq, pWhi, pWlo, nW);
    gemm_mma<<<gg, 256, GEMM_SMEM>>>(pAhi, pAlo, pWhi, pWlo, pQ);
    // K projection
    split_bf16<<<csA, cb>>>(k,  pAhi, pAlo, nA);
    split_bf16<<<csW, cb>>>(Wk, pWhi, pWlo, nW);
    gemm_mma<<<gg, 256, GEMM_SMEM>>>(pAhi, pAlo, pWhi, pWlo, pK);
    // V projection
    split_bf16<<<csA, cb>>>(v,  pAhi, pAlo, nA);
    split_bf16<<<csW, cb>>>(Wv, pWhi, pWlo, nW);
    gemm_mma<<<gg, 256, GEMM_SMEM>>>(pAhi, pAlo, pWhi, pWlo, pV);

    // attention
    attn_kernel<<<ga, 256, ATTN_SMEM>>>(mask);

    // output projection
    split_bf16<<<csA, cb>>>(pMH, pAhi, pAlo, nA);
    split_bf16<<<csW, cb>>>(Wo, pWhi, pWlo, nW);
    gemm_mma<<<gg, 256, GEMM_SMEM>>>(pAhi, pAlo, pWhi, pWlo, out);
}

// round 9
// speedup vs baseline: 2.5629x; 1.9635x over previous
#include <cuda_runtime.h>
#include <cuda_bf16.h>
#include <cstdint>

#define B_   4
#define S_   2048
#define DM_  1024
#define H_   16
#define DK_  64

// ---------------- scratch (device globals; allocation-free) ----------------
__device__ __nv_bfloat16 g_Qhi[B_*S_*DM_];   // projected Q/K/V, bf16 hi/lo split
__device__ __nv_bfloat16 g_Qlo[B_*S_*DM_];
__device__ __nv_bfloat16 g_Khi[B_*S_*DM_];
__device__ __nv_bfloat16 g_Klo[B_*S_*DM_];
__device__ __nv_bfloat16 g_Vhi[B_*S_*DM_];
__device__ __nv_bfloat16 g_Vlo[B_*S_*DM_];
__device__ __nv_bfloat16 g_MHhi[B_*S_*DM_];  // merged heads, split
__device__ __nv_bfloat16 g_MHlo[B_*S_*DM_];
__device__ __nv_bfloat16 g_Ahi[B_*S_*DM_];   // split activations (GEMM A)
__device__ __nv_bfloat16 g_Alo[B_*S_*DM_];
__device__ __nv_bfloat16 g_Whi[DM_*DM_];     // split weights
__device__ __nv_bfloat16 g_Wlo[DM_*DM_];

// ---------------- helpers (baseline PTX only: valid at .target sm_103) -----
__device__ __forceinline__ uint32_t smem_u32(const void* p) {
    uint32_t a;
    asm("{ .reg .u64 t; cvta.to.shared.u64 t, %1; cvt.u32.u64 %0, t; }"
        : "=r"(a) : "l"(p));
    return a;
}
__device__ __forceinline__ void ldsm4(uint32_t* r, uint32_t a) {
    asm volatile("ldmatrix.sync.aligned.m8n8.x4.shared.b16 {%0,%1,%2,%3}, [%4];"
                 : "=r"(r[0]), "=r"(r[1]), "=r"(r[2]), "=r"(r[3]) : "r"(a));
}
__device__ __forceinline__ void ldsm4t(uint32_t* r, uint32_t a) {
    asm volatile("ldmatrix.sync.aligned.m8n8.x4.trans.shared.b16 {%0,%1,%2,%3}, [%4];"
                 : "=r"(r[0]), "=r"(r[1]), "=r"(r[2]), "=r"(r[3]) : "r"(a));
}
__device__ __forceinline__ void mma16816(float* d, const uint32_t* a,
                                         const uint32_t* b) {
    asm volatile(
        "mma.sync.aligned.m16n8k16.row.col.f32.bf16.bf16.f32 "
        "{%0,%1,%2,%3}, {%4,%5,%6,%7}, {%8,%9}, {%0,%1,%2,%3};"
        : "+f"(d[0]), "+f"(d[1]), "+f"(d[2]), "+f"(d[3])
        : "r"(a[0]), "r"(a[1]), "r"(a[2]), "r"(a[3]), "r"(b[0]), "r"(b[1]));
}
#define CP16(dst, src) \
    asm volatile("cp.async.cg.shared.global [%0], [%1], 16;" \
                 :: "r"(dst), "l"(src))
#define CPCOMMIT() asm volatile("cp.async.commit_group;" ::: "memory")
#define CPWAIT(n)  asm volatile("cp.async.wait_group %0;" :: "n"(n) : "memory")

__device__ __forceinline__ uint32_t pack_bf16(float x, float y) {
    __nv_bfloat162 t(__float2bfloat16(x), __float2bfloat16(y));
    return *(uint32_t*)&t;
}
__device__ __forceinline__ uint32_t pack_bf16_res(float x, float y,
                                                  uint32_t hi) {
    __nv_bfloat162 h = *(__nv_bfloat162*)&hi;
    return pack_bf16(x - __bfloat162float(h.x), y - __bfloat162float(h.y));
}

// ---------------------------------------------------------------------------
// split fp32 x -> bf16 hi + lo
// ---------------------------------------------------------------------------
__global__ void split_bf16(const float* __restrict__ x,
                           __nv_bfloat16* __restrict__ hi,
                           __nv_bfloat16* __restrict__ lo, int n) {
    int i = (blockIdx.x * blockDim.x + threadIdx.x) * 4;
    if (i >= n) return;
    float4 v = *(const float4*)(x + i);
    uint32_t h0 = pack_bf16(v.x, v.y), h1 = pack_bf16(v.z, v.w);
    uint32_t l0 = pack_bf16_res(v.x, v.y, h0), l1 = pack_bf16_res(v.z, v.w, h1);
    *(uint32_t*)(hi + i) = h0; *(uint32_t*)(hi + i + 2) = h1;
    *(uint32_t*)(lo + i) = l0; *(uint32_t*)(lo + i + 2) = l1;
}

// ---------------------------------------------------------------------------
// mma.sync bf16x3 GEMM: C[M,1024] = A[M,1024] * W^T.
// mode 0: fp32 C.  mode 1: write bf16 hi/lo split to Chi/Clo.
// ---------------------------------------------------------------------------
#define BK          32
#define LDSTR       40
#define MAT_ELEMS   (128 * LDSTR)
#define STAGE_ELEMS (4 * MAT_ELEMS)
#define GEMM_SMEM   (2 * STAGE_ELEMS * 2)

__global__ __launch_bounds__(256) void gemm_mma(
    const __nv_bfloat16* __restrict__ Ahi, const __nv_bfloat16* __restrict__ Alo,
    const __nv_bfloat16* __restrict__ Bhi, const __nv_bfloat16* __restrict__ Blo,
    float* __restrict__ C, __nv_bfloat16* __restrict__ Chi,
    __nv_bfloat16* __restrict__ Clo, int mode) {
    extern __shared__ __nv_bfloat16 smem[];
    const uint32_t sbase = smem_u32(smem);

    const int tid = threadIdx.x;
    const int wid = tid >> 5;
    const int lid = tid & 31;
    const int wm  = wid >> 1;
    const int wn  = wid & 1;
    const int bm  = blockIdx.y * 128;
    const int bn  = blockIdx.x * 128;

    const int lrow = tid >> 2;
    const int lseg = tid & 3;
    const __nv_bfloat16* gsrc[4];
    gsrc[0] = Ahi + (size_t)(bm + lrow) * 1024 + lseg * 8;
    gsrc[1] = Alo + (size_t)(bm + lrow) * 1024 + lseg * 8;
    gsrc[2] = Bhi + (size_t)(bn + lrow) * 1024 + lseg * 8;
    gsrc[3] = Blo + (size_t)(bn + lrow) * 1024 + lseg * 8;
    const uint32_t sdst = sbase + (uint32_t)(lrow * LDSTR + lseg * 8) * 2;

    const int ra = ((lid >> 3) & 1) * 8 + (lid & 7);
    const int ca = (lid >> 4) * 8;
    const uint32_t aoff = (uint32_t)((wm * 32 + ra) * LDSTR + ca);
    const int rb = (lid >> 4) * 8 + (lid & 7);
    const int cb = ((lid >> 3) & 1) * 8;
    const uint32_t boff = (uint32_t)((wn * 64 + rb) * LDSTR + cb);

    float acc[2][8][4];
#pragma unroll
    for (int t = 0; t < 2; t++)
#pragma unroll
        for (int j = 0; j < 8; j++)
#pragma unroll
            for (int e = 0; e < 4; e++) acc[t][j][e] = 0.f;

#pragma unroll
    for (int m = 0; m < 4; m++)
#pragma unroll
        for (int r2 = 0; r2 < 2; r2++)
            CP16(sdst + (uint32_t)(m * MAT_ELEMS + r2 * 64 * LDSTR) * 2,
                 gsrc[m] + (size_t)r2 * 64 * 1024);
    CPCOMMIT();

    for (int kc = 0; kc < 32; ++kc) {
        __syncthreads();
        if (kc < 31) {
            const int k0 = (kc + 1) * BK;
            const uint32_t sb2 = sdst + (uint32_t)(((kc + 1) & 1) * STAGE_ELEMS) * 2;
#pragma unroll
            for (int m = 0; m < 4; m++)
#pragma unroll
                for (int r2 = 0; r2 < 2; r2++)
                    CP16(sb2 + (uint32_t)(m * MAT_ELEMS + r2 * 64 * LDSTR) * 2,
                         gsrc[m] + (size_t)r2 * 64 * 1024 + k0);
            CPCOMMIT();
            CPWAIT(1);
        } else {
            CPWAIT(0);
        }
        __syncthreads();

        const uint32_t mb   = sbase + (uint32_t)((kc & 1) * STAGE_ELEMS) * 2;
        const uint32_t bAhi = mb;
        const uint32_t bAlo = mb + MAT_ELEMS * 2;
        const uint32_t bWhi = mb + 2 * MAT_ELEMS * 2;
        const uint32_t bWlo = mb + 3 * MAT_ELEMS * 2;

#pragma unroll
        for (int k16 = 0; k16 < 2; k16++) {
            const uint32_t kadd = (uint32_t)(k16 * 16) * 2;
            uint32_t ah[2][4], al[2][4], bh[8][2], bl[8][2];
#pragma unroll
            for (int t = 0; t < 2; t++) {
                const uint32_t ao = (aoff + t * 16 * LDSTR) * 2 + kadd;
                ldsm4(ah[t], bAhi + ao);
                ldsm4(al[t], bAlo + ao);
            }
#pragma unroll
            for (int jp = 0; jp < 4; jp++) {
                const uint32_t bo = (boff + jp * 16 * LDSTR) * 2 + kadd;
                uint32_t r[4];
                ldsm4(r, bWhi + bo);
                bh[2*jp][0] = r[0]; bh[2*jp][1] = r[1];
                bh[2*jp+1][0] = r[2]; bh[2*jp+1][1] = r[3];
                ldsm4(r, bWlo + bo);
                bl[2*jp][0] = r[0]; bl[2*jp][1] = r[1];
                bl[2*jp+1][0] = r[2]; bl[2*jp+1][1] = r[3];
            }
#pragma unroll
            for (int t = 0; t < 2; t++)
#pragma unroll
                for (int j = 0; j < 8; j++) {
                    mma16816(acc[t][j], ah[t], bh[j]);
                    mma16816(acc[t][j], ah[t], bl[j]);
                    mma16816(acc[t][j], al[t], bh[j]);
                }
        }
    }

    const int r0 = bm + wm * 32 + (lid >> 2);
    const int c0 = bn + wn * 64 + (lid & 3) * 2;
    if (mode == 0) {
#pragma unroll
        for (int t = 0; t < 2; t++)
#pragma unroll
            for (int j = 0; j < 8; j++) {
                float* p0 = C + (size_t)(r0 + t * 16) * 1024 + c0 + j * 8;
                float* p1 = p0 + 8 * 1024;
                *(float2*)p0 = make_float2(acc[t][j][0], acc[t][j][1]);
                *(float2*)p1 = make_float2(acc[t][j][2], acc[t][j][3]);
            }
    } else {
#pragma unroll
        for (int t = 0; t < 2; t++)
#pragma unroll
            for (int j = 0; j < 8; j++) {
                size_t i0 = (size_t)(r0 + t * 16) * 1024 + c0 + j * 8;
                size_t i1 = i0 + 8 * 1024;
                uint32_t h0 = pack_bf16(acc[t][j][0], acc[t][j][1]);
                uint32_t h1 = pack_bf16(acc[t][j][2], acc[t][j][3]);
                *(uint32_t*)(Chi + i0) = h0;
                *(uint32_t*)(Chi + i1) = h1;
                *(uint32_t*)(Clo + i0) = pack_bf16_res(acc[t][j][0], acc[t][j][1], h0);
                *(uint32_t*)(Clo + i1) = pack_bf16_res(acc[t][j][2], acc[t][j][3], h1);
            }
    }
}

// ---------------------------------------------------------------------------
// Tensor-core flash attention (mma.sync, bf16x3 for QK^T and PV).
// Grid (S/128, H, B), 256 threads = 8 warps x 16 q-rows.
// Key tiles of 64, cp.async double-buffered K/V hi/lo.
// ---------------------------------------------------------------------------
#define ALDS      72                        // padded bf16 row stride (144B)
#define KV_MAT    (64 * ALDS)
#define KV_STAGE  (4 * KV_MAT)
#define Q_OFF     (2 * KV_STAGE)
#define Q_MAT     (128 * ALDS)
#define MSK_OFF   ((Q_OFF + 2 * Q_MAT) * 2)
#define ATTN_SMEM (MSK_OFF + 2 * 64 * 4)

__global__ __launch_bounds__(256) void attn_mma(const int* __restrict__ mask) {
    extern __shared__ __nv_bfloat16 sm[];
    const uint32_t sb = smem_u32(sm);
    int* msk = (int*)((char*)sm + MSK_OFF);

    const int b   = blockIdx.z;
    const int h   = blockIdx.y;
    const int q0  = blockIdx.x * 128;
    const int tid = threadIdx.x;
    const int w   = tid >> 5;
    const int lid = tid & 31;

    const size_t rowb = (size_t)b * 2048;
    const __nv_bfloat16* Qh = g_Qhi + (rowb + q0) * 1024 + h * 64;
    const __nv_bfloat16* Ql = g_Qlo + (rowb + q0) * 1024 + h * 64;
    const __nv_bfloat16* Kh = g_Khi + rowb * 1024 + h * 64;
    const __nv_bfloat16* Kl = g_Klo + rowb * 1024 + h * 64;
    const __nv_bfloat16* Vh = g_Vhi + rowb * 1024 + h * 64;
    const __nv_bfloat16* Vl = g_Vlo + rowb * 1024 + h * 64;

    // ---- prologue: Q (hi/lo) + KV stage0 + mask0 ----
    {
        const int qrow = tid >> 1;
        const int qs0  = (tid & 1) * 4;
#pragma unroll
        for (int i = 0; i < 4; i++) {
            int seg = qs0 + i;
            CP16(sb + (uint32_t)(Q_OFF + qrow * ALDS + seg * 8) * 2,
                 Qh + (size_t)qrow * 1024 + seg * 8);
            CP16(sb + (uint32_t)(Q_OFF + Q_MAT + qrow * ALDS + seg * 8) * 2,
                 Ql + (size_t)qrow * 1024 + seg * 8);
        }
        const int krow = tid >> 2;
        const int ks0  = (tid & 3) * 2;
#pragma unroll
        for (int e = 0; e < 2; e++) {
            int seg = ks0 + e;
            uint32_t d0 = sb + (uint32_t)(krow * ALDS + seg * 8) * 2;
            const size_t g = (size_t)krow * 1024 + seg * 8;
            CP16(d0,                  Kh + g);
            CP16(d0 + KV_MAT * 2,     Kl + g);
            CP16(d0 + 2 * KV_MAT * 2, Vh + g);
            CP16(d0 + 3 * KV_MAT * 2, Vl + g);
        }
        if (tid < 64) msk[tid] = mask[b * 2048 + tid];
        CPCOMMIT();
        CPWAIT(0);
        __syncthreads();
    }

    // ---- Q fragments (held in registers for the whole kernel) ----
    const int ra = ((lid >> 3) & 1) * 8 + (lid & 7);
    const int ca = (lid >> 4) * 8;
    uint32_t qh[4][4], ql[4][4];
#pragma unroll
    for (int t = 0; t < 4; t++) {
        uint32_t ao = sb + (uint32_t)(Q_OFF + (w * 16 + ra) * ALDS + t * 16 + ca) * 2;
        ldsm4(qh[t], ao);
        ldsm4(ql[t], ao + Q_MAT * 2);
    }

    float O[8][4];
#pragma unroll
    for (int j = 0; j < 8; j++)
#pragma unroll
        for (int e = 0; e < 4; e++) O[j][e] = 0.f;
    float m0 = -1e30f, m1 = -1e30f, l0 = 0.f, l1 = 0.f;

    const int rbB = (lid >> 4) * 8 + (lid & 7);
    const int cbB = ((lid >> 3) & 1) * 8;
    const int cb2 = (lid & 3) * 2;

    for (int kc = 0; kc < 32; kc++) {
        __syncthreads();
        if (kc < 31) {
            const int k0 = (kc + 1) * 64;
            const uint32_t st = sb + (uint32_t)(((kc + 1) & 1) * KV_STAGE) * 2;
            const int krow = tid >> 2;
            const int ks0  = (tid & 3) * 2;
#pragma unroll
            for (int e = 0; e < 2; e++) {
                int seg = ks0 + e;
                uint32_t d0 = st + (uint32_t)(krow * ALDS + seg * 8) * 2;
                const size_t g = (size_t)(k0 + krow) * 1024 + seg * 8;
                CP16(d0,                  Kh + g);
                CP16(d0 + KV_MAT * 2,     Kl + g);
                CP16(d0 + 2 * KV_MAT * 2, Vh + g);
                CP16(d0 + 3 * KV_MAT * 2, Vl + g);
            }
            if (tid < 64) msk[((kc + 1) & 1) * 64 + tid] = mask[b * 2048 + k0 + tid];
            CPCOMMIT();
            CPWAIT(1);
        } else {
            CPWAIT(0);
        }
        __syncthreads();

        const uint32_t st = sb + (uint32_t)((kc & 1) * KV_STAGE) * 2;

        // ---- S = Q K^T (3-term) ----
        float sC[8][4];
#pragma unroll
        for (int j = 0; j < 8; j++)
#pragma unroll
            for (int e = 0; e < 4; e++) sC[j][e] = 0.f;
#pragma unroll
        for (int t = 0; t < 4; t++) {
            uint32_t kh2[8][2], kl2[8][2];
#pragma unroll
            for (int np = 0; np < 4; np++) {
                uint32_t bo = st + (uint32_t)((np * 16 + rbB) * ALDS + t * 16 + cbB) * 2;
                uint32_t r[4];
                ldsm4(r, bo);
                kh2[2*np][0] = r[0]; kh2[2*np][1] = r[1];
                kh2[2*np+1][0] = r[2]; kh2[2*np+1][1] = r[3];
                ldsm4(r, bo + KV_MAT * 2);
                kl2[2*np][0] = r[0]; kl2[2*np][1] = r[1];
                kl2[2*np+1][0] = r[2]; kl2[2*np+1][1] = r[3];
            }
#pragma unroll
            for (int j = 0; j < 8; j++) {
                mma16816(sC[j], qh[t], kh2[j]);
                mma16816(sC[j], qh[t], kl2[j]);
                mma16816(sC[j], ql[t], kh2[j]);
            }
        }

        // ---- mask + scale + online softmax ----
        const int* mkc = msk + (kc & 1) * 64;
        float rmax0 = -1e30f, rmax1 = -1e30f;
#pragma unroll
        for (int j = 0; j < 8; j++) {
            bool z0 = (mkc[j * 8 + cb2] == 0);
            bool z1 = (mkc[j * 8 + cb2 + 1] == 0);
            sC[j][0] = z0 ? -1e9f : sC[j][0] * 0.125f;
            sC[j][1] = z1 ? -1e9f : sC[j][1] * 0.125f;
            sC[j][2] = z0 ? -1e9f : sC[j][2] * 0.125f;
            sC[j][3] = z1 ? -1e9f : sC[j][3] * 0.125f;
            rmax0 = fmaxf(rmax0, fmaxf(sC[j][0], sC[j][1]));
            rmax1 = fmaxf(rmax1, fmaxf(sC[j][2], sC[j][3]));
        }
        rmax0 = fmaxf(rmax0, __shfl_xor_sync(0xffffffffu, rmax0, 1));
        rmax0 = fmaxf(rmax0, __shfl_xor_sync(0xffffffffu, rmax0, 2));
        rmax1 = fmaxf(rmax1, __shfl_xor_sync(0xffffffffu, rmax1, 1));
        rmax1 = fmaxf(rmax1, __shfl_xor_sync(0xffffffffu, rmax1, 2));

        float mn0 = fmaxf(m0, rmax0), mn1 = fmaxf(m1, rmax1);
        float corr0 = __expf(m0 - mn0), corr1 = __expf(m1 - mn1);
        m0 = mn0; m1 = mn1;
        float rs0 = 0.f, rs1 = 0.f;
#pragma unroll
        for (int j = 0; j < 8; j++) {
            sC[j][0] = __expf(sC[j][0] - mn0);
            sC[j][1] = __expf(sC[j][1] - mn0);
            sC[j][2] = __expf(sC[j][2] - mn1);
            sC[j][3] = __expf(sC[j][3] - mn1);
            rs0 += sC[j][0] + sC[j][1];
            rs1 += sC[j][2] + sC[j][3];
        }
        rs0 += __shfl_xor_sync(0xffffffffu, rs0, 1);
        rs0 += __shfl_xor_sync(0xffffffffu, rs0, 2);
        rs1 += __shfl_xor_sync(0xffffffffu, rs1, 1);
        rs1 += __shfl_xor_sync(0xffffffffu, rs1, 2);
        l0 = l0 * corr0 + rs0;
        l1 = l1 * corr1 + rs1;
#pragma unroll
        for (int j = 0; j < 8; j++) {
            O[j][0] *= corr0; O[j][1] *= corr0;
            O[j][2] *= corr1; O[j][3] *= corr1;
        }

        // ---- O += P V (3-term); P packed straight from sC registers ----
#pragma unroll
        for (int t = 0; t < 4; t++) {
            uint32_t ph[4], pl[4];
            ph[0] = pack_bf16(sC[2*t][0],   sC[2*t][1]);
            ph[1] = pack_bf16(sC[2*t][2],   sC[2*t][3]);
            ph[2] = pack_bf16(sC[2*t+1][0], sC[2*t+1][1]);
            ph[3] = pack_bf16(sC[2*t+1][2], sC[2*t+1][3]);
            pl[0] = pack_bf16_res(sC[2*t][0],   sC[2*t][1],   ph[0]);
            pl[1] = pack_bf16_res(sC[2*t][2],   sC[2*t][3],   ph[1]);
            pl[2] = pack_bf16_res(sC[2*t+1][0], sC[2*t+1][1], ph[2]);
            pl[3] = pack_bf16_res(sC[2*t+1][2], sC[2*t+1][3], ph[3]);

            uint32_t vh2[8][2], vl2[8][2];
#pragma unroll
            for (int dp = 0; dp < 4; dp++) {
                uint32_t vo = st + (uint32_t)(2 * KV_MAT) * 2 +
                              (uint32_t)((t * 16 + ra) * ALDS + dp * 16 + ca) * 2;
                uint32_t r[4];
                ldsm4t(r, vo);
                vh2[2*dp][0] = r[0]; vh2[2*dp][1] = r[1];
                vh2[2*dp+1][0] = r[2]; vh2[2*dp+1][1] = r[3];
                ldsm4t(r, vo + KV_MAT * 2);
                vl2[2*dp][0] = r[0]; vl2[2*dp][1] = r[1];
                vl2[2*dp+1][0] = r[2]; vl2[2*dp+1][1] = r[3];
            }
#pragma unroll
            for (int jd = 0; jd < 8; jd++) {
                mma16816(O[jd], ph, vh2[jd]);
                mma16816(O[jd], ph, vl2[jd]);
                mma16816(O[jd], pl, vh2[jd]);
            }
        }
    }

    // ---- epilogue: O/l -> MH hi/lo bf16 ----
    const float inv0 = 1.f / l0, inv1 = 1.f / l1;
    const int row0 = q0 + w * 16 + (lid >> 2);
    const size_t base0 = (rowb + row0) * 1024 + h * 64 + cb2;
#pragma unroll
    for (int jd = 0; jd < 8; jd++) {
        float x0 = O[jd][0] * inv0, x1 = O[jd][1] * inv0;
        float x2 = O[jd][2] * inv1, x3 = O[jd][3] * inv1;
        uint32_t h0 = pack_bf16(x0, x1), h1 = pack_bf16(x2, x3);
        *(uint32_t*)(g_MHhi + base0 + jd * 8)            = h0;
        *(uint32_t*)(g_MHhi + base0 + 8 * 1024 + jd * 8) = h1;
        *(uint32_t*)(g_MHlo + base0 + jd * 8)            = pack_bf16_res(x0, x1, h0);
        *(uint32_t*)(g_MHlo + base0 + 8 * 1024 + jd * 8) = pack_bf16_res(x2, x3, h1);
    }
}

// ---------------------------------------------------------------------------
extern "C" void kernel_launch(void* const* d_in, const int* in_sizes, int n_in,
                              void* d_out, int out_size) {
    const float* q    = (const float*)d_in[0];
    const float* k    = (const float*)d_in[1];
    const float* v    = (const float*)d_in[2];
    const int*   mask = (const int*)  d_in[3];
    const float* Wq   = (const float*)d_in[4];
    const float* Wk   = (const float*)d_in[5];
    const float* Wv   = (const float*)d_in[6];
    const float* Wo   = (const float*)d_in[7];
    float* out = (float*)d_out;

    __nv_bfloat16 *pQh,*pQl,*pKh,*pKl,*pVh,*pVl,*pMh,*pMl,*pAh,*pAl,*pWh,*pWl;
    cudaGetSymbolAddress((void**)&pQh, g_Qhi); cudaGetSymbolAddress((void**)&pQl, g_Qlo);
    cudaGetSymbolAddress((void**)&pKh, g_Khi); cudaGetSymbolAddress((void**)&pKl, g_Klo);
    cudaGetSymbolAddress((void**)&pVh, g_Vhi); cudaGetSymbolAddress((void**)&pVl, g_Vlo);
    cudaGetSymbolAddress((void**)&pMh, g_MHhi); cudaGetSymbolAddress((void**)&pMl, g_MHlo);
    cudaGetSymbolAddress((void**)&pAh, g_Ahi); cudaGetSymbolAddress((void**)&pAl, g_Alo);
    cudaGetSymbolAddress((void**)&pWh, g_Whi); cudaGetSymbolAddress((void**)&pWl, g_Wlo);

    cudaFuncSetAttribute(gemm_mma,
                         cudaFuncAttributeMaxDynamicSharedMemorySize, GEMM_SMEM);
    cudaFuncSetAttribute(attn_mma,
                         cudaFuncAttributeMaxDynamicSharedMemorySize, ATTN_SMEM);

    const int nA = B_ * S_ * DM_;
    const int nW = DM_ * DM_;
    dim3 csA((nA / 4 + 255) / 256), cb(256);
    dim3 csW((nW / 4 + 255) / 256);
    dim3 gg(8, 64);
    dim3 ga(16, 16, 4);

    // Q projection -> bf16 split
    split_bf16<<<csA, cb>>>(q,  pAh, pAl, nA);
    split_bf16<<<csW, cb>>>(Wq, pWh, pWl, nW);
    gemm_mma<<<gg, 256, GEMM_SMEM>>>(pAh, pAl, pWh, pWl, nullptr, pQh, pQl, 1);
    // K projection
    split_bf16<<<csA, cb>>>(k,  pAh, pAl, nA);
    split_bf16<<<csW, cb>>>(Wk, pWh, pWl, nW);
    gemm_mma<<<gg, 256, GEMM_SMEM>>>(pAh, pAl, pWh, pWl, nullptr, pKh, pKl, 1);
    // V projection
    split_bf16<<<csA, cb>>>(v,  pAh, pAl, nA);
    split_bf16<<<csW, cb>>>(Wv, pWh, pWl, nW);
    gemm_mma<<<gg, 256, GEMM_SMEM>>>(pAh, pAl, pWh, pWl, nullptr, pVh, pVl, 1);

    // attention (tensor-core flash)
    attn_mma<<<ga, 256, ATTN_SMEM>>>(mask);

    // output projection (fp32 out)
    split_bf16<<<csW, cb>>>(Wo, pWh, pWl, nW);
    gemm_mma<<<gg, 256, GEMM_SMEM>>>(pMh, pMl, pWh, pWl, out, nullptr, nullptr, 0);
}

// round 12
// speedup vs baseline: 2.9796x; 1.1626x over previous
#include <cuda_runtime.h>
#include <cuda_bf16.h>
#include <cstdint>

#define B_   4
#define S_   2048
#define DM_  1024
#define H_   16
#define DK_  64
#define NA_  (B_*S_*DM_)      // 8,388,608
#define NW_  (DM_*DM_)        // 1,048,576

// ---------------- scratch (device globals; allocation-free) ----------------
__device__ __nv_bfloat16 g_A3hi[3*NA_];    // split activations q,k,v (z-stacked)
__device__ __nv_bfloat16 g_A3lo[3*NA_];
__device__ __nv_bfloat16 g_W4hi[4*NW_];    // split weights Wq,Wk,Wv,Wo
__device__ __nv_bfloat16 g_W4lo[4*NW_];
__device__ __nv_bfloat16 g_QKVhi[3*NA_];   // projected Q,K,V (z-stacked)
__device__ __nv_bfloat16 g_QKVlo[3*NA_];
__device__ __nv_bfloat16 g_MHhi[NA_];      // merged heads
__device__ __nv_bfloat16 g_MHlo[NA_];

// ---------------- helpers (baseline PTX only: valid at .target sm_103) -----
__device__ __forceinline__ uint32_t smem_u32(const void* p) {
    uint32_t a;
    asm("{ .reg .u64 t; cvta.to.shared.u64 t, %1; cvt.u32.u64 %0, t; }"
        : "=r"(a) : "l"(p));
    return a;
}
__device__ __forceinline__ void ldsm4(uint32_t* r, uint32_t a) {
    asm volatile("ldmatrix.sync.aligned.m8n8.x4.shared.b16 {%0,%1,%2,%3}, [%4];"
                 : "=r"(r[0]), "=r"(r[1]), "=r"(r[2]), "=r"(r[3]) : "r"(a));
}
__device__ __forceinline__ void ldsm4t(uint32_t* r, uint32_t a) {
    asm volatile("ldmatrix.sync.aligned.m8n8.x4.trans.shared.b16 {%0,%1,%2,%3}, [%4];"
                 : "=r"(r[0]), "=r"(r[1]), "=r"(r[2]), "=r"(r[3]) : "r"(a));
}
__device__ __forceinline__ void mma16816(float* d, const uint32_t* a,
                                         const uint32_t* b) {
    asm volatile(
        "mma.sync.aligned.m16n8k16.row.col.f32.bf16.bf16.f32 "
        "{%0,%1,%2,%3}, {%4,%5,%6,%7}, {%8,%9}, {%0,%1,%2,%3};"
        : "+f"(d[0]), "+f"(d[1]), "+f"(d[2]), "+f"(d[3])
        : "r"(a[0]), "r"(a[1]), "r"(a[2]), "r"(a[3]), "r"(b[0]), "r"(b[1]));
}
#define CP16(dst, src) \
    asm volatile("cp.async.cg.shared.global [%0], [%1], 16;" \
                 :: "r"(dst), "l"(src))
#define CPCOMMIT() asm volatile("cp.async.commit_group;" ::: "memory")
#define CPWAIT(n)  asm volatile("cp.async.wait_group %0;" :: "n"(n) : "memory")

__device__ __forceinline__ uint32_t pack_bf16(float x, float y) {
    __nv_bfloat162 t(__float2bfloat16(x), __float2bfloat16(y));
    return *(uint32_t*)&t;
}
__device__ __forceinline__ uint32_t pack_bf16_res(float x, float y,
                                                  uint32_t hi) {
    __nv_bfloat162 h = *(__nv_bfloat162*)&hi;
    return pack_bf16(x - __bfloat162float(h.x), y - __bfloat162float(h.y));
}

// ---------------------------------------------------------------------------
// batched split: slice blockIdx.y of up to 4 fp32 srcs -> bf16 hi/lo at y*n
// ---------------------------------------------------------------------------
__global__ void split_multi(const float* __restrict__ s0,
                            const float* __restrict__ s1,
                            const float* __restrict__ s2,
                            const float* __restrict__ s3,
                            __nv_bfloat16* __restrict__ hi,
                            __nv_bfloat16* __restrict__ lo, int n) {
    const int y = blockIdx.y;
    const float* x = (y == 0) ? s0 : (y == 1) ? s1 : (y == 2) ? s2 : s3;
    int i = (blockIdx.x * blockDim.x + threadIdx.x) * 4;
    if (i >= n) return;
    hi += (size_t)y * n;
    lo += (size_t)y * n;
    float4 v = *(const float4*)(x + i);
    uint32_t h0 = pack_bf16(v.x, v.y), h1 = pack_bf16(v.z, v.w);
    uint32_t l0 = pack_bf16_res(v.x, v.y, h0), l1 = pack_bf16_res(v.z, v.w, h1);
    *(uint32_t*)(hi + i) = h0; *(uint32_t*)(hi + i + 2) = h1;
    *(uint32_t*)(lo + i) = l0; *(uint32_t*)(lo + i + 2) = l1;
}

// ---------------------------------------------------------------------------
// mma.sync bf16x3 GEMM: C[M,1024] = A[M,1024] * W^T, batched over blockIdx.z.
// mode 0: fp32 C.  mode 1: bf16 hi/lo split to Chi/Clo (+z*NA_).
// 128x128 CTA tile, BK=32, single-sync double-buffered cp.async.
// ---------------------------------------------------------------------------
#define BK          32
#define LDSTR       40
#define MAT_ELEMS   (128 * LDSTR)
#define STAGE_ELEMS (4 * MAT_ELEMS)
#define GEMM_SMEM   (2 * STAGE_ELEMS * 2)

__global__ __launch_bounds__(256, 2) void gemm_mma(
    const __nv_bfloat16* __restrict__ Ahi, const __nv_bfloat16* __restrict__ Alo,
    const __nv_bfloat16* __restrict__ Whi, const __nv_bfloat16* __restrict__ Wlo,
    float* __restrict__ C, __nv_bfloat16* __restrict__ Chi,
    __nv_bfloat16* __restrict__ Clo, int mode) {
    extern __shared__ __nv_bfloat16 smem[];
    const uint32_t sbase = smem_u32(smem);

    const int z = blockIdx.z;
    Ahi += (size_t)z * NA_; Alo += (size_t)z * NA_;
    Whi += (size_t)z * NW_; Wlo += (size_t)z * NW_;

    const int tid = threadIdx.x;
    const int wid = tid >> 5;
    const int lid = tid & 31;
    const int wm  = wid >> 1;
    const int wn  = wid & 1;
    const int bm  = blockIdx.y * 128;
    const int bn  = blockIdx.x * 128;

    const int lrow = tid >> 2;
    const int lseg = tid & 3;
    const __nv_bfloat16* gsrc[4];
    gsrc[0] = Ahi + (size_t)(bm + lrow) * 1024 + lseg * 8;
    gsrc[1] = Alo + (size_t)(bm + lrow) * 1024 + lseg * 8;
    gsrc[2] = Whi + (size_t)(bn + lrow) * 1024 + lseg * 8;
    gsrc[3] = Wlo + (size_t)(bn + lrow) * 1024 + lseg * 8;
    const uint32_t sdst = sbase + (uint32_t)(lrow * LDSTR + lseg * 8) * 2;

    const int ra = ((lid >> 3) & 1) * 8 + (lid & 7);
    const int ca = (lid >> 4) * 8;
    const uint32_t aoff = (uint32_t)((wm * 32 + ra) * LDSTR + ca);
    const int rb = (lid >> 4) * 8 + (lid & 7);
    const int cb = ((lid >> 3) & 1) * 8;
    const uint32_t boff = (uint32_t)((wn * 64 + rb) * LDSTR + cb);

    float acc[2][8][4];
#pragma unroll
    for (int t = 0; t < 2; t++)
#pragma unroll
        for (int j = 0; j < 8; j++)
#pragma unroll
            for (int e = 0; e < 4; e++) acc[t][j][e] = 0.f;

    // prologue: stage 0
#pragma unroll
    for (int m = 0; m < 4; m++)
#pragma unroll
        for (int r2 = 0; r2 < 2; r2++)
            CP16(sdst + (uint32_t)(m * MAT_ELEMS + r2 * 64 * LDSTR) * 2,
                 gsrc[m] + (size_t)r2 * 64 * 1024);
    CPCOMMIT();

    for (int kc = 0; kc < 32; ++kc) {
        CPWAIT(0);
        __syncthreads();            // stage kc ready; slot kc^1 free everywhere
        if (kc < 31) {
            const int k0 = (kc + 1) * BK;
            const uint32_t sb2 = sdst + (uint32_t)(((kc + 1) & 1) * STAGE_ELEMS) * 2;
#pragma unroll
            for (int m = 0; m < 4; m++)
#pragma unroll
                for (int r2 = 0; r2 < 2; r2++)
                    CP16(sb2 + (uint32_t)(m * MAT_ELEMS + r2 * 64 * LDSTR) * 2,
                         gsrc[m] + (size_t)r2 * 64 * 1024 + k0);
            CPCOMMIT();
        }

        const uint32_t mb   = sbase + (uint32_t)((kc & 1) * STAGE_ELEMS) * 2;
        const uint32_t bAhi = mb;
        const uint32_t bAlo = mb + MAT_ELEMS * 2;
        const uint32_t bWhi = mb + 2 * MAT_ELEMS * 2;
        const uint32_t bWlo = mb + 3 * MAT_ELEMS * 2;

#pragma unroll
        for (int k16 = 0; k16 < 2; k16++) {
            const uint32_t kadd = (uint32_t)(k16 * 16) * 2;
            uint32_t ah[2][4], al[2][4];
#pragma unroll
            for (int t = 0; t < 2; t++) {
                const uint32_t ao = (aoff + t * 16 * LDSTR) * 2 + kadd;
                ldsm4(ah[t], bAhi + ao);
                ldsm4(al[t], bAlo + ao);
            }
#pragma unroll
            for (int jp = 0; jp < 4; jp++) {
                const uint32_t bo = (boff + jp * 16 * LDSTR) * 2 + kadd;
                uint32_t bh4[4], bl4[4];
                ldsm4(bh4, bWhi + bo);
                ldsm4(bl4, bWlo + bo);
#pragma unroll
                for (int t = 0; t < 2; t++) {
                    mma16816(acc[t][2*jp],   ah[t], bh4);
                    mma16816(acc[t][2*jp],   ah[t], bl4);
                    mma16816(acc[t][2*jp],   al[t], bh4);
                    mma16816(acc[t][2*jp+1], ah[t], bh4 + 2);
                    mma16816(acc[t][2*jp+1], ah[t], bl4 + 2);
                    mma16816(acc[t][2*jp+1], al[t], bh4 + 2);
                }
            }
        }
    }

    const int r0 = bm + wm * 32 + (lid >> 2);
    const int c0 = bn + wn * 64 + (lid & 3) * 2;
    if (mode == 0) {
#pragma unroll
        for (int t = 0; t < 2; t++)
#pragma unroll
            for (int j = 0; j < 8; j++) {
                float* p0 = C + (size_t)(r0 + t * 16) * 1024 + c0 + j * 8;
                float* p1 = p0 + 8 * 1024;
                *(float2*)p0 = make_float2(acc[t][j][0], acc[t][j][1]);
                *(float2*)p1 = make_float2(acc[t][j][2], acc[t][j][3]);
            }
    } else {
        Chi += (size_t)z * NA_; Clo += (size_t)z * NA_;
#pragma unroll
        for (int t = 0; t < 2; t++)
#pragma unroll
            for (int j = 0; j < 8; j++) {
                size_t i0 = (size_t)(r0 + t * 16) * 1024 + c0 + j * 8;
                size_t i1 = i0 + 8 * 1024;
                uint32_t h0 = pack_bf16(acc[t][j][0], acc[t][j][1]);
                uint32_t h1 = pack_bf16(acc[t][j][2], acc[t][j][3]);
                *(uint32_t*)(Chi + i0) = h0;
                *(uint32_t*)(Chi + i1) = h1;
                *(uint32_t*)(Clo + i0) = pack_bf16_res(acc[t][j][0], acc[t][j][1], h0);
                *(uint32_t*)(Clo + i1) = pack_bf16_res(acc[t][j][2], acc[t][j][3], h1);
            }
    }
}

// ---------------------------------------------------------------------------
// Tensor-core flash attention (mma.sync, bf16x3 for QK^T and PV).
// Grid (S/128, H, B), 256 threads = 8 warps x 16 q-rows.
// Key tiles of 64, single-sync double-buffered cp.async K/V hi/lo.
// ---------------------------------------------------------------------------
#define ALDS      72
#define KV_MAT    (64 * ALDS)
#define KV_STAGE  (4 * KV_MAT)
#define Q_OFF     (2 * KV_STAGE)
#define Q_MAT     (128 * ALDS)
#define MSK_OFF   ((Q_OFF + 2 * Q_MAT) * 2)
#define ATTN_SMEM (MSK_OFF + 2 * 64 * 4)

__global__ __launch_bounds__(256) void attn_mma(const int* __restrict__ mask) {
    extern __shared__ __nv_bfloat16 sm[];
    const uint32_t sb = smem_u32(sm);
    int* msk = (int*)((char*)sm + MSK_OFF);

    const int b   = blockIdx.z;
    const int h   = blockIdx.y;
    const int q0  = blockIdx.x * 128;
    const int tid = threadIdx.x;
    const int w   = tid >> 5;
    const int lid = tid & 31;

    const size_t rowb = (size_t)b * 2048;
    const __nv_bfloat16* Qh = g_QKVhi + (rowb + q0) * 1024 + h * 64;
    const __nv_bfloat16* Ql = g_QKVlo + (rowb + q0) * 1024 + h * 64;
    const __nv_bfloat16* Kh = g_QKVhi + (size_t)NA_ + rowb * 1024 + h * 64;
    const __nv_bfloat16* Kl = g_QKVlo + (size_t)NA_ + rowb * 1024 + h * 64;
    const __nv_bfloat16* Vh = g_QKVhi + (size_t)2 * NA_ + rowb * 1024 + h * 64;
    const __nv_bfloat16* Vl = g_QKVlo + (size_t)2 * NA_ + rowb * 1024 + h * 64;

    // ---- prologue: Q (hi/lo) + KV stage0 + mask0 ----
    {
        const int qrow = tid >> 1;
        const int qs0  = (tid & 1) * 4;
#pragma unroll
        for (int i = 0; i < 4; i++) {
            int seg = qs0 + i;
            CP16(sb + (uint32_t)(Q_OFF + qrow * ALDS + seg * 8) * 2,
                 Qh + (size_t)qrow * 1024 + seg * 8);
            CP16(sb + (uint32_t)(Q_OFF + Q_MAT + qrow * ALDS + seg * 8) * 2,
                 Ql + (size_t)qrow * 1024 + seg * 8);
        }
        const int krow = tid >> 2;
        const int ks0  = (tid & 3) * 2;
#pragma unroll
        for (int e = 0; e < 2; e++) {
            int seg = ks0 + e;
            uint32_t d0 = sb + (uint32_t)(krow * ALDS + seg * 8) * 2;
            const size_t g = (size_t)krow * 1024 + seg * 8;
            CP16(d0,                  Kh + g);
            CP16(d0 + KV_MAT * 2,     Kl + g);
            CP16(d0 + 2 * KV_MAT * 2, Vh + g);
            CP16(d0 + 3 * KV_MAT * 2, Vl + g);
        }
        if (tid < 64) msk[tid] = mask[b * 2048 + tid];
        CPCOMMIT();
        CPWAIT(0);
        __syncthreads();
    }

    // ---- Q fragments (registers, whole kernel) ----
    const int ra = ((lid >> 3) & 1) * 8 + (lid & 7);
    const int ca = (lid >> 4) * 8;
    uint32_t qh[4][4], ql[4][4];
#pragma unroll
    for (int t = 0; t < 4; t++) {
        uint32_t ao = sb + (uint32_t)(Q_OFF + (w * 16 + ra) * ALDS + t * 16 + ca) * 2;
        ldsm4(qh[t], ao);
        ldsm4(ql[t], ao + Q_MAT * 2);
    }

    float O[8][4];
#pragma unroll
    for (int j = 0; j < 8; j++)
#pragma unroll
        for (int e = 0; e < 4; e++) O[j][e] = 0.f;
    float m0 = -1e30f, m1 = -1e30f, l0 = 0.f, l1 = 0.f;

    const int rbB = (lid >> 4) * 8 + (lid & 7);
    const int cbB = ((lid >> 3) & 1) * 8;
    const int cb2 = (lid & 3) * 2;

    for (int kc = 0; kc < 32; kc++) {
        CPWAIT(0);
        __syncthreads();
        if (kc < 31) {
            const int k0 = (kc + 1) * 64;
            const uint32_t st2 = sb + (uint32_t)(((kc + 1) & 1) * KV_STAGE) * 2;
            const int krow = tid >> 2;
            const int ks0  = (tid & 3) * 2;
#pragma unroll
            for (int e = 0; e < 2; e++) {
                int seg = ks0 + e;
                uint32_t d0 = st2 + (uint32_t)(krow * ALDS + seg * 8) * 2;
                const size_t g = (size_t)(k0 + krow) * 1024 + seg * 8;
                CP16(d0,                  Kh + g);
                CP16(d0 + KV_MAT * 2,     Kl + g);
                CP16(d0 + 2 * KV_MAT * 2, Vh + g);
                CP16(d0 + 3 * KV_MAT * 2, Vl + g);
            }
            if (tid < 64) msk[((kc + 1) & 1) * 64 + tid] = mask[b * 2048 + k0 + tid];
            CPCOMMIT();
        }

        const uint32_t st = sb + (uint32_t)((kc & 1) * KV_STAGE) * 2;

        // ---- S = Q K^T (3-term) ----
        float sC[8][4];
#pragma unroll
        for (int j = 0; j < 8; j++)
#pragma unroll
            for (int e = 0; e < 4; e++) sC[j][e] = 0.f;
#pragma unroll
        for (int t = 0; t < 4; t++) {
#pragma unroll
            for (int np = 0; np < 4; np++) {
                uint32_t bo = st + (uint32_t)((np * 16 + rbB) * ALDS + t * 16 + cbB) * 2;
                uint32_t kh4[4], kl4[4];
                ldsm4(kh4, bo);
                ldsm4(kl4, bo + KV_MAT * 2);
                mma16816(sC[2*np],   qh[t], kh4);
                mma16816(sC[2*np],   qh[t], kl4);
                mma16816(sC[2*np],   ql[t], kh4);
                mma16816(sC[2*np+1], qh[t], kh4 + 2);
                mma16816(sC[2*np+1], qh[t], kl4 + 2);
                mma16816(sC[2*np+1], ql[t], kh4 + 2);
            }
        }

        // ---- mask + scale + online softmax ----
        const int* mkc = msk + (kc & 1) * 64;
        float rmax0 = -1e30f, rmax1 = -1e30f;
#pragma unroll
        for (int j = 0; j < 8; j++) {
            bool z0 = (mkc[j * 8 + cb2] == 0);
            bool z1 = (mkc[j * 8 + cb2 + 1] == 0);
            sC[j][0] = z0 ? -1e9f : sC[j][0] * 0.125f;
            sC[j][1] = z1 ? -1e9f : sC[j][1] * 0.125f;
            sC[j][2] = z0 ? -1e9f : sC[j][2] * 0.125f;
            sC[j][3] = z1 ? -1e9f : sC[j][3] * 0.125f;
            rmax0 = fmaxf(rmax0, fmaxf(sC[j][0], sC[j][1]));
            rmax1 = fmaxf(rmax1, fmaxf(sC[j][2], sC[j][3]));
        }
        rmax0 = fmaxf(rmax0, __shfl_xor_sync(0xffffffffu, rmax0, 1));
        rmax0 = fmaxf(rmax0, __shfl_xor_sync(0xffffffffu, rmax0, 2));
        rmax1 = fmaxf(rmax1, __shfl_xor_sync(0xffffffffu, rmax1, 1));
        rmax1 = fmaxf(rmax1, __shfl_xor_sync(0xffffffffu, rmax1, 2));

        float mn0 = fmaxf(m0, rmax0), mn1 = fmaxf(m1, rmax1);
        float corr0 = __expf(m0 - mn0), corr1 = __expf(m1 - mn1);
        m0 = mn0; m1 = mn1;
        float rs0 = 0.f, rs1 = 0.f;
#pragma unroll
        for (int j = 0; j < 8; j++) {
            sC[j][0] = __expf(sC[j][0] - mn0);
            sC[j][1] = __expf(sC[j][1] - mn0);
            sC[j][2] = __expf(sC[j][2] - mn1);
            sC[j][3] = __expf(sC[j][3] - mn1);
            rs0 += sC[j][0] + sC[j][1];
            rs1 += sC[j][2] + sC[j][3];
        }
        rs0 += __shfl_xor_sync(0xffffffffu, rs0, 1);
        rs0 += __shfl_xor_sync(0xffffffffu, rs0, 2);
        rs1 += __shfl_xor_sync(0xffffffffu, rs1, 1);
        rs1 += __shfl_xor_sync(0xffffffffu, rs1, 2);
        l0 = l0 * corr0 + rs0;
        l1 = l1 * corr1 + rs1;
#pragma unroll
        for (int j = 0; j < 8; j++) {
            O[j][0] *= corr0; O[j][1] *= corr0;
            O[j][2] *= corr1; O[j][3] *= corr1;
        }

        // ---- O += P V (3-term); P packed straight from sC registers ----
#pragma unroll
        for (int t = 0; t < 4; t++) {
            uint32_t ph[4], pl[4];
            ph[0] = pack_bf16(sC[2*t][0],   sC[2*t][1]);
            ph[1] = pack_bf16(sC[2*t][2],   sC[2*t][3]);
            ph[2] = pack_bf16(sC[2*t+1][0], sC[2*t+1][1]);
            ph[3] = pack_bf16(sC[2*t+1][2], sC[2*t+1][3]);
            pl[0] = pack_bf16_res(sC[2*t][0],   sC[2*t][1],   ph[0]);
            pl[1] = pack_bf16_res(sC[2*t][2],   sC[2*t][3],   ph[1]);
            pl[2] = pack_bf16_res(sC[2*t+1][0], sC[2*t+1][1], ph[2]);
            pl[3] = pack_bf16_res(sC[2*t+1][2], sC[2*t+1][3], ph[3]);

#pragma unroll
            for (int dp = 0; dp < 4; dp++) {
                uint32_t vo = st + (uint32_t)(2 * KV_MAT) * 2 +
                              (uint32_t)((t * 16 + ra) * ALDS + dp * 16 + ca) * 2;
                uint32_t vh4[4], vl4[4];
                ldsm4t(vh4, vo);
                ldsm4t(vl4, vo + KV_MAT * 2);
                mma16816(O[2*dp],   ph, vh4);
                mma16816(O[2*dp],   ph, vl4);
                mma16816(O[2*dp],   pl, vh4);
                mma16816(O[2*dp+1], ph, vh4 + 2);
                mma16816(O[2*dp+1], ph, vl4 + 2);
                mma16816(O[2*dp+1], pl, vh4 + 2);
            }
        }
    }

    // ---- epilogue: O/l -> MH hi/lo bf16 ----
    const float inv0 = 1.f / l0, inv1 = 1.f / l1;
    const int row0 = q0 + w * 16 + (lid >> 2);
    const size_t base0 = (rowb + row0) * 1024 + h * 64 + cb2;
#pragma unroll
    for (int jd = 0; jd < 8; jd++) {
        float x0 = O[jd][0] * inv0, x1 = O[jd][1] * inv0;
        float x2 = O[jd][2] * inv1, x3 = O[jd][3] * inv1;
        uint32_t h0 = pack_bf16(x0, x1), h1 = pack_bf16(x2, x3);
        *(uint32_t*)(g_MHhi + base0 + jd * 8)            = h0;
        *(uint32_t*)(g_MHhi + base0 + 8 * 1024 + jd * 8) = h1;
        *(uint32_t*)(g_MHlo + base0 + jd * 8)            = pack_bf16_res(x0, x1, h0);
        *(uint32_t*)(g_MHlo + base0 + 8 * 1024 + jd * 8) = pack_bf16_res(x2, x3, h1);
    }
}

// ---------------------------------------------------------------------------
extern "C" void kernel_launch(void* const* d_in, const int* in_sizes, int n_in,
                              void* d_out, int out_size) {
    const float* q    = (const float*)d_in[0];
    const float* k    = (const float*)d_in[1];
    const float* v    = (const float*)d_in[2];
    const int*   mask = (const int*)  d_in[3];
    const float* Wq   = (const float*)d_in[4];
    const float* Wk   = (const float*)d_in[5];
    const float* Wv   = (const float*)d_in[6];
    const float* Wo   = (const float*)d_in[7];
    float* out = (float*)d_out;

    __nv_bfloat16 *pAh, *pAl, *pWh, *pWl, *pQh, *pQl, *pMh, *pMl;
    cudaGetSymbolAddress((void**)&pAh, g_A3hi);
    cudaGetSymbolAddress((void**)&pAl, g_A3lo);
    cudaGetSymbolAddress((void**)&pWh, g_W4hi);
    cudaGetSymbolAddress((void**)&pWl, g_W4lo);
    cudaGetSymbolAddress((void**)&pQh, g_QKVhi);
    cudaGetSymbolAddress((void**)&pQl, g_QKVlo);
    cudaGetSymbolAddress((void**)&pMh, g_MHhi);
    cudaGetSymbolAddress((void**)&pMl, g_MHlo);

    cudaFuncSetAttribute(gemm_mma,
                         cudaFuncAttributeMaxDynamicSharedMemorySize, GEMM_SMEM);
    cudaFuncSetAttribute(attn_mma,
                         cudaFuncAttributeMaxDynamicSharedMemorySize, ATTN_SMEM);

    dim3 cb(256);
    dim3 csA((NA_ / 4 + 255) / 256, 3);      // q,k,v activations
    dim3 csW((NW_ / 4 + 255) / 256, 4);      // Wq,Wk,Wv,Wo
    dim3 gg3(8, 64, 3);                      // batched Q/K/V projections
    dim3 gg1(8, 64, 1);                      // output projection
    dim3 ga(16, 16, 4);                      // attention

    split_multi<<<csA, cb>>>(q, k, v, v, pAh, pAl, NA_);
    split_multi<<<csW, cb>>>(Wq, Wk, Wv, Wo, pWh, pWl, NW_);
    gemm_mma<<<gg3, 256, GEMM_SMEM>>>(pAh, pAl, pWh, pWl,
                                      nullptr, pQh, pQl, 1);
    attn_mma<<<ga, 256, ATTN_SMEM>>>(mask);
    gemm_mma<<<gg1, 256, GEMM_SMEM>>>(pMh, pMl, pWh + (size_t)3 * NW_,
                                      pWl + (size_t)3 * NW_,
                                      out, nullptr, nullptr, 0);
}

// round 15
// speedup vs baseline: 3.1983x; 1.0734x over previous
#include <cuda_runtime.h>
#include <cuda_bf16.h>
#include <cstdint>

#define B_   4
#define S_   2048
#define DM_  1024
#define H_   16
#define DK_  64
#define NA_  (B_*S_*DM_)      // 8,388,608
#define NW_  (DM_*DM_)        // 1,048,576

// ---------------- scratch (device globals; allocation-free) ----------------
__device__ __nv_bfloat16 g_A3hi[3*NA_];    // split activations q,k,v (z-stacked)
__device__ __nv_bfloat16 g_A3lo[3*NA_];
__device__ __nv_bfloat16 g_W4hi[4*NW_];    // split weights Wq,Wk,Wv,Wo
__device__ __nv_bfloat16 g_W4lo[4*NW_];
__device__ __nv_bfloat16 g_QKVhi[3*NA_];   // projected Q,K,V (z-stacked)
__device__ __nv_bfloat16 g_QKVlo[3*NA_];
__device__ __nv_bfloat16 g_MHhi[NA_];      // merged heads
__device__ __nv_bfloat16 g_MHlo[NA_];

// ---------------- helpers (baseline PTX only: valid at .target sm_103) -----
__device__ __forceinline__ uint32_t smem_u32(const void* p) {
    uint32_t a;
    asm("{ .reg .u64 t; cvta.to.shared.u64 t, %1; cvt.u32.u64 %0, t; }"
        : "=r"(a) : "l"(p));
    return a;
}
__device__ __forceinline__ void ldsm4(uint32_t* r, uint32_t a) {
    asm volatile("ldmatrix.sync.aligned.m8n8.x4.shared.b16 {%0,%1,%2,%3}, [%4];"
                 : "=r"(r[0]), "=r"(r[1]), "=r"(r[2]), "=r"(r[3]) : "r"(a));
}
__device__ __forceinline__ void ldsm4t(uint32_t* r, uint32_t a) {
    asm volatile("ldmatrix.sync.aligned.m8n8.x4.trans.shared.b16 {%0,%1,%2,%3}, [%4];"
                 : "=r"(r[0]), "=r"(r[1]), "=r"(r[2]), "=r"(r[3]) : "r"(a));
}
__device__ __forceinline__ void mma16816(float* d, const uint32_t* a,
                                         const uint32_t* b) {
    asm volatile(
        "mma.sync.aligned.m16n8k16.row.col.f32.bf16.bf16.f32 "
        "{%0,%1,%2,%3}, {%4,%5,%6,%7}, {%8,%9}, {%0,%1,%2,%3};"
        : "+f"(d[0]), "+f"(d[1]), "+f"(d[2]), "+f"(d[3])
        : "r"(a[0]), "r"(a[1]), "r"(a[2]), "r"(a[3]), "r"(b[0]), "r"(b[1]));
}
#define CP16(dst, src) \
    asm volatile("cp.async.cg.shared.global [%0], [%1], 16;" \
                 :: "r"(dst), "l"(src))
#define CPCOMMIT() asm volatile("cp.async.commit_group;" ::: "memory")
#define CPWAIT(n)  asm volatile("cp.async.wait_group %0;" :: "n"(n) : "memory")

__device__ __forceinline__ uint32_t pack_bf16(float x, float y) {
    __nv_bfloat162 t(__float2bfloat16(x), __float2bfloat16(y));
    return *(uint32_t*)&t;
}
__device__ __forceinline__ uint32_t pack_bf16_res(float x, float y,
                                                  uint32_t hi) {
    __nv_bfloat162 h = *(__nv_bfloat162*)&hi;
    return pack_bf16(x - __bfloat162float(h.x), y - __bfloat162float(h.y));
}

// ---------------------------------------------------------------------------
// batched split: slice blockIdx.y of up to 4 fp32 srcs -> bf16 hi/lo at y*n
// ---------------------------------------------------------------------------
__global__ void split_multi(const float* __restrict__ s0,
                            const float* __restrict__ s1,
                            const float* __restrict__ s2,
                            const float* __restrict__ s3,
                            __nv_bfloat16* __restrict__ hi,
                            __nv_bfloat16* __restrict__ lo, int n) {
    const int y = blockIdx.y;
    const float* x = (y == 0) ? s0 : (y == 1) ? s1 : (y == 2) ? s2 : s3;
    int i = (blockIdx.x * blockDim.x + threadIdx.x) * 4;
    if (i >= n) return;
    hi += (size_t)y * n;
    lo += (size_t)y * n;
    float4 v = *(const float4*)(x + i);
    uint32_t h0 = pack_bf16(v.x, v.y), h1 = pack_bf16(v.z, v.w);
    uint32_t l0 = pack_bf16_res(v.x, v.y, h0), l1 = pack_bf16_res(v.z, v.w, h1);
    *(uint32_t*)(hi + i) = h0; *(uint32_t*)(hi + i + 2) = h1;
    *(uint32_t*)(lo + i) = l0; *(uint32_t*)(lo + i + 2) = l1;
}

// ---------------------------------------------------------------------------
// mma.sync bf16x3 GEMM: C[M,1024] = A[M,1024] * W^T, batched over blockIdx.z.
// mode 0: fp32 C.  mode 1: bf16 hi/lo split to Chi/Clo (+z*NA_).
// 128x128 CTA tile, BK=32, single-sync double-buffered cp.async.
// ---------------------------------------------------------------------------
#define BK          32
#define LDSTR       40
#define MAT_ELEMS   (128 * LDSTR)
#define STAGE_ELEMS (4 * MAT_ELEMS)
#define GEMM_SMEM   (2 * STAGE_ELEMS * 2)

__global__ __launch_bounds__(256, 2) void gemm_mma(
    const __nv_bfloat16* __restrict__ Ahi, const __nv_bfloat16* __restrict__ Alo,
    const __nv_bfloat16* __restrict__ Whi, const __nv_bfloat16* __restrict__ Wlo,
    float* __restrict__ C, __nv_bfloat16* __restrict__ Chi,
    __nv_bfloat16* __restrict__ Clo, int mode) {
    extern __shared__ __nv_bfloat16 smem[];
    const uint32_t sbase = smem_u32(smem);

    const int z = blockIdx.z;
    Ahi += (size_t)z * NA_; Alo += (size_t)z * NA_;
    Whi += (size_t)z * NW_; Wlo += (size_t)z * NW_;

    const int tid = threadIdx.x;
    const int wid = tid >> 5;
    const int lid = tid & 31;
    const int wm  = wid >> 1;
    const int wn  = wid & 1;
    const int bm  = blockIdx.y * 128;
    const int bn  = blockIdx.x * 128;

    const int lrow = tid >> 2;
    const int lseg = tid & 3;
    const __nv_bfloat16* gsrc[4];
    gsrc[0] = Ahi + (size_t)(bm + lrow) * 1024 + lseg * 8;
    gsrc[1] = Alo + (size_t)(bm + lrow) * 1024 + lseg * 8;
    gsrc[2] = Whi + (size_t)(bn + lrow) * 1024 + lseg * 8;
    gsrc[3] = Wlo + (size_t)(bn + lrow) * 1024 + lseg * 8;
    const uint32_t sdst = sbase + (uint32_t)(lrow * LDSTR + lseg * 8) * 2;

    const int ra = ((lid >> 3) & 1) * 8 + (lid & 7);
    const int ca = (lid >> 4) * 8;
    const uint32_t aoff = (uint32_t)((wm * 32 + ra) * LDSTR + ca);
    const int rb = (lid >> 4) * 8 + (lid & 7);
    const int cb = ((lid >> 3) & 1) * 8;
    const uint32_t boff = (uint32_t)((wn * 64 + rb) * LDSTR + cb);

    float acc[2][8][4];
#pragma unroll
    for (int t = 0; t < 2; t++)
#pragma unroll
        for (int j = 0; j < 8; j++)
#pragma unroll
            for (int e = 0; e < 4; e++) acc[t][j][e] = 0.f;

    // prologue: stage 0
#pragma unroll
    for (int m = 0; m < 4; m++)
#pragma unroll
        for (int r2 = 0; r2 < 2; r2++)
            CP16(sdst + (uint32_t)(m * MAT_ELEMS + r2 * 64 * LDSTR) * 2,
                 gsrc[m] + (size_t)r2 * 64 * 1024);
    CPCOMMIT();

    for (int kc = 0; kc < 32; ++kc) {
        CPWAIT(0);
        __syncthreads();            // stage kc ready; slot kc^1 free everywhere
        if (kc < 31) {
            const int k0 = (kc + 1) * BK;
            const uint32_t sb2 = sdst + (uint32_t)(((kc + 1) & 1) * STAGE_ELEMS) * 2;
#pragma unroll
            for (int m = 0; m < 4; m++)
#pragma unroll
                for (int r2 = 0; r2 < 2; r2++)
                    CP16(sb2 + (uint32_t)(m * MAT_ELEMS + r2 * 64 * LDSTR) * 2,
                         gsrc[m] + (size_t)r2 * 64 * 1024 + k0);
            CPCOMMIT();
        }

        const uint32_t mb   = sbase + (uint32_t)((kc & 1) * STAGE_ELEMS) * 2;
        const uint32_t bAhi = mb;
        const uint32_t bAlo = mb + MAT_ELEMS * 2;
        const uint32_t bWhi = mb + 2 * MAT_ELEMS * 2;
        const uint32_t bWlo = mb + 3 * MAT_ELEMS * 2;

#pragma unroll
        for (int k16 = 0; k16 < 2; k16++) {
            const uint32_t kadd = (uint32_t)(k16 * 16) * 2;
            uint32_t ah[2][4], al[2][4];
#pragma unroll
            for (int t = 0; t < 2; t++) {
                const uint32_t ao = (aoff + t * 16 * LDSTR) * 2 + kadd;
                ldsm4(ah[t], bAhi + ao);
                ldsm4(al[t], bAlo + ao);
            }
#pragma unroll
            for (int jp = 0; jp < 4; jp++) {
                const uint32_t bo = (boff + jp * 16 * LDSTR) * 2 + kadd;
                uint32_t bh4[4], bl4[4];
                ldsm4(bh4, bWhi + bo);
                ldsm4(bl4, bWlo + bo);
#pragma unroll
                for (int t = 0; t < 2; t++) {
                    mma16816(acc[t][2*jp],   ah[t], bh4);
                    mma16816(acc[t][2*jp],   ah[t], bl4);
                    mma16816(acc[t][2*jp],   al[t], bh4);
                    mma16816(acc[t][2*jp+1], ah[t], bh4 + 2);
                    mma16816(acc[t][2*jp+1], ah[t], bl4 + 2);
                    mma16816(acc[t][2*jp+1], al[t], bh4 + 2);
                }
            }
        }
    }

    const int r0 = bm + wm * 32 + (lid >> 2);
    const int c0 = bn + wn * 64 + (lid & 3) * 2;
    if (mode == 0) {
#pragma unroll
        for (int t = 0; t < 2; t++)
#pragma unroll
            for (int j = 0; j < 8; j++) {
                float* p0 = C + (size_t)(r0 + t * 16) * 1024 + c0 + j * 8;
                float* p1 = p0 + 8 * 1024;
                *(float2*)p0 = make_float2(acc[t][j][0], acc[t][j][1]);
                *(float2*)p1 = make_float2(acc[t][j][2], acc[t][j][3]);
            }
    } else {
        Chi += (size_t)z * NA_; Clo += (size_t)z * NA_;
#pragma unroll
        for (int t = 0; t < 2; t++)
#pragma unroll
            for (int j = 0; j < 8; j++) {
                size_t i0 = (size_t)(r0 + t * 16) * 1024 + c0 + j * 8;
                size_t i1 = i0 + 8 * 1024;
                uint32_t h0 = pack_bf16(acc[t][j][0], acc[t][j][1]);
                uint32_t h1 = pack_bf16(acc[t][j][2], acc[t][j][3]);
                *(uint32_t*)(Chi + i0) = h0;
                *(uint32_t*)(Chi + i1) = h1;
                *(uint32_t*)(Clo + i0) = pack_bf16_res(acc[t][j][0], acc[t][j][1], h0);
                *(uint32_t*)(Clo + i1) = pack_bf16_res(acc[t][j][2], acc[t][j][3], h1);
            }
    }
}

// ---------------------------------------------------------------------------
// Tensor-core flash attention (mma.sync, bf16x3 for QK^T and PV).
// Grid (S/128, H, B), 256 threads = 8 warps x 16 q-rows.
// Key tiles of 64, single-sync double-buffered cp.async K/V hi/lo.
// Q fragments reloaded from smem per tile (regs <= 128 -> 2 CTAs/SM).
// ---------------------------------------------------------------------------
#define ALDS      72
#define KV_MAT    (64 * ALDS)
#define KV_STAGE  (4 * KV_MAT)
#define Q_OFF     (2 * KV_STAGE)
#define Q_MAT     (128 * ALDS)
#define MSK_OFF   ((Q_OFF + 2 * Q_MAT) * 2)
#define ATTN_SMEM (MSK_OFF + 2 * 64 * 4)
#define LOG2E     1.4426950408889634f

__global__ __launch_bounds__(256, 2) void attn_mma(const int* __restrict__ mask) {
    extern __shared__ __nv_bfloat16 sm[];
    const uint32_t sb = smem_u32(sm);
    int* msk = (int*)((char*)sm + MSK_OFF);

    const int b   = blockIdx.z;
    const int h   = blockIdx.y;
    const int q0  = blockIdx.x * 128;
    const int tid = threadIdx.x;
    const int w   = tid >> 5;
    const int lid = tid & 31;

    const size_t rowb = (size_t)b * 2048;
    const __nv_bfloat16* Qh = g_QKVhi + (rowb + q0) * 1024 + h * 64;
    const __nv_bfloat16* Ql = g_QKVlo + (rowb + q0) * 1024 + h * 64;
    const __nv_bfloat16* Kh = g_QKVhi + (size_t)NA_ + rowb * 1024 + h * 64;
    const __nv_bfloat16* Kl = g_QKVlo + (size_t)NA_ + rowb * 1024 + h * 64;
    const __nv_bfloat16* Vh = g_QKVhi + (size_t)2 * NA_ + rowb * 1024 + h * 64;
    const __nv_bfloat16* Vl = g_QKVlo + (size_t)2 * NA_ + rowb * 1024 + h * 64;

    // ---- prologue: Q (hi/lo) + KV stage0 + mask0 ----
    {
        const int qrow = tid >> 1;
        const int qs0  = (tid & 1) * 4;
#pragma unroll
        for (int i = 0; i < 4; i++) {
            int seg = qs0 + i;
            CP16(sb + (uint32_t)(Q_OFF + qrow * ALDS + seg * 8) * 2,
                 Qh + (size_t)qrow * 1024 + seg * 8);
            CP16(sb + (uint32_t)(Q_OFF + Q_MAT + qrow * ALDS + seg * 8) * 2,
                 Ql + (size_t)qrow * 1024 + seg * 8);
        }
        const int krow = tid >> 2;
        const int ks0  = (tid & 3) * 2;
#pragma unroll
        for (int e = 0; e < 2; e++) {
            int seg = ks0 + e;
            uint32_t d0 = sb + (uint32_t)(krow * ALDS + seg * 8) * 2;
            const size_t g = (size_t)krow * 1024 + seg * 8;
            CP16(d0,                  Kh + g);
            CP16(d0 + KV_MAT * 2,     Kl + g);
            CP16(d0 + 2 * KV_MAT * 2, Vh + g);
            CP16(d0 + 3 * KV_MAT * 2, Vl + g);
        }
        if (tid < 64) msk[tid] = mask[b * 2048 + tid];
        CPCOMMIT();
        CPWAIT(0);
        __syncthreads();
    }

    const int ra = ((lid >> 3) & 1) * 8 + (lid & 7);
    const int ca = (lid >> 4) * 8;
    const uint32_t qbase = sb + (uint32_t)(Q_OFF + (w * 16 + ra) * ALDS + ca) * 2;

    float O[8][4];
#pragma unroll
    for (int j = 0; j < 8; j++)
#pragma unroll
        for (int e = 0; e < 4; e++) O[j][e] = 0.f;
    float m0 = -1e30f, m1 = -1e30f, l0 = 0.f, l1 = 0.f;

    const int rbB = (lid >> 4) * 8 + (lid & 7);
    const int cbB = ((lid >> 3) & 1) * 8;
    const int cb2 = (lid & 3) * 2;

    for (int kc = 0; kc < 32; kc++) {
        CPWAIT(0);
        __syncthreads();
        if (kc < 31) {
            const int k0 = (kc + 1) * 64;
            const uint32_t st2 = sb + (uint32_t)(((kc + 1) & 1) * KV_STAGE) * 2;
            const int krow = tid >> 2;
            const int ks0  = (tid & 3) * 2;
#pragma unroll
            for (int e = 0; e < 2; e++) {
                int seg = ks0 + e;
                uint32_t d0 = st2 + (uint32_t)(krow * ALDS + seg * 8) * 2;
                const size_t g = (size_t)(k0 + krow) * 1024 + seg * 8;
                CP16(d0,                  Kh + g);
                CP16(d0 + KV_MAT * 2,     Kl + g);
                CP16(d0 + 2 * KV_MAT * 2, Vh + g);
                CP16(d0 + 3 * KV_MAT * 2, Vl + g);
            }
            if (tid < 64) msk[((kc + 1) & 1) * 64 + tid] = mask[b * 2048 + k0 + tid];
            CPCOMMIT();
        }

        const uint32_t st = sb + (uint32_t)((kc & 1) * KV_STAGE) * 2;

        // ---- S = Q K^T (3-term); Q fragments reloaded from smem ----
        float sC[8][4];
#pragma unroll
        for (int j = 0; j < 8; j++)
#pragma unroll
            for (int e = 0; e < 4; e++) sC[j][e] = 0.f;
#pragma unroll
        for (int t = 0; t < 4; t++) {
            uint32_t qh4[4], ql4[4];
            ldsm4(qh4, qbase + (uint32_t)(t * 16) * 2);
            ldsm4(ql4, qbase + (uint32_t)(Q_MAT + t * 16) * 2);
#pragma unroll
            for (int np = 0; np < 4; np++) {
                uint32_t bo = st + (uint32_t)((np * 16 + rbB) * ALDS + t * 16 + cbB) * 2;
                uint32_t kh4[4], kl4[4];
                ldsm4(kh4, bo);
                ldsm4(kl4, bo + KV_MAT * 2);
                mma16816(sC[2*np],   qh4, kh4);
                mma16816(sC[2*np],   qh4, kl4);
                mma16816(sC[2*np],   ql4, kh4);
                mma16816(sC[2*np+1], qh4, kh4 + 2);
                mma16816(sC[2*np+1], qh4, kl4 + 2);
                mma16816(sC[2*np+1], ql4, kh4 + 2);
            }
        }

        // ---- mask + scale + online softmax (base-2) ----
        const int* mkc = msk + (kc & 1) * 64;
        const float sc2 = 0.125f * LOG2E;
        float rmax0 = -1e30f, rmax1 = -1e30f;
#pragma unroll
        for (int j = 0; j < 8; j++) {
            bool z0 = (mkc[j * 8 + cb2] == 0);
            bool z1 = (mkc[j * 8 + cb2 + 1] == 0);
            sC[j][0] = z0 ? -1e9f : sC[j][0] * sc2;
            sC[j][1] = z1 ? -1e9f : sC[j][1] * sc2;
            sC[j][2] = z0 ? -1e9f : sC[j][2] * sc2;
            sC[j][3] = z1 ? -1e9f : sC[j][3] * sc2;
            rmax0 = fmaxf(rmax0, fmaxf(sC[j][0], sC[j][1]));
            rmax1 = fmaxf(rmax1, fmaxf(sC[j][2], sC[j][3]));
        }
        rmax0 = fmaxf(rmax0, __shfl_xor_sync(0xffffffffu, rmax0, 1));
        rmax0 = fmaxf(rmax0, __shfl_xor_sync(0xffffffffu, rmax0, 2));
        rmax1 = fmaxf(rmax1, __shfl_xor_sync(0xffffffffu, rmax1, 1));
        rmax1 = fmaxf(rmax1, __shfl_xor_sync(0xffffffffu, rmax1, 2));

        float mn0 = fmaxf(m0, rmax0), mn1 = fmaxf(m1, rmax1);
        float corr0 = exp2f(m0 - mn0), corr1 = exp2f(m1 - mn1);
        m0 = mn0; m1 = mn1;
        float rs0 = 0.f, rs1 = 0.f;
#pragma unroll
        for (int j = 0; j < 8; j++) {
            sC[j][0] = exp2f(sC[j][0] - mn0);
            sC[j][1] = exp2f(sC[j][1] - mn0);
            sC[j][2] = exp2f(sC[j][2] - mn1);
            sC[j][3] = exp2f(sC[j][3] - mn1);
            rs0 += sC[j][0] + sC[j][1];
            rs1 += sC[j][2] + sC[j][3];
        }
        rs0 += __shfl_xor_sync(0xffffffffu, rs0, 1);
        rs0 += __shfl_xor_sync(0xffffffffu, rs0, 2);
        rs1 += __shfl_xor_sync(0xffffffffu, rs1, 1);
        rs1 += __shfl_xor_sync(0xffffffffu, rs1, 2);
        l0 = l0 * corr0 + rs0;
        l1 = l1 * corr1 + rs1;
#pragma unroll
        for (int j = 0; j < 8; j++) {
            O[j][0] *= corr0; O[j][1] *= corr0;
            O[j][2] *= corr1; O[j][3] *= corr1;
        }

        // ---- O += P V (3-term); P packed straight from sC registers ----
#pragma unroll
        for (int t = 0; t < 4; t++) {
            uint32_t ph[4], pl[4];
            ph[0] = pack_bf16(sC[2*t][0],   sC[2*t][1]);
            ph[1] = pack_bf16(sC[2*t][2],   sC[2*t][3]);
            ph[2] = pack_bf16(sC[2*t+1][0], sC[2*t+1][1]);
            ph[3] = pack_bf16(sC[2*t+1][2], sC[2*t+1][3]);
            pl[0] = pack_bf16_res(sC[2*t][0],   sC[2*t][1],   ph[0]);
            pl[1] = pack_bf16_res(sC[2*t][2],   sC[2*t][3],   ph[1]);
            pl[2] = pack_bf16_res(sC[2*t+1][0], sC[2*t+1][1], ph[2]);
            pl[3] = pack_bf16_res(sC[2*t+1][2], sC[2*t+1][3], ph[3]);

#pragma unroll
            for (int dp = 0; dp < 4; dp++) {
                uint32_t vo = st + (uint32_t)(2 * KV_MAT) * 2 +
                              (uint32_t)((t * 16 + ra) * ALDS + dp * 16 + ca) * 2;
                uint32_t vh4[4], vl4[4];
                ldsm4t(vh4, vo);
                ldsm4t(vl4, vo + KV_MAT * 2);
                mma16816(O[2*dp],   ph, vh4);
                mma16816(O[2*dp],   ph, vl4);
                mma16816(O[2*dp],   pl, vh4);
                mma16816(O[2*dp+1], ph, vh4 + 2);
                mma16816(O[2*dp+1], ph, vl4 + 2);
                mma16816(O[2*dp+1], pl, vh4 + 2);
            }
        }
    }

    // ---- epilogue: O/l -> MH hi/lo bf16 ----
    const float inv0 = 1.f / l0, inv1 = 1.f / l1;
    const int row0 = q0 + w * 16 + (lid >> 2);
    const size_t base0 = (rowb + row0) * 1024 + h * 64 + cb2;
#pragma unroll
    for (int jd = 0; jd < 8; jd++) {
        float x0 = O[jd][0] * inv0, x1 = O[jd][1] * inv0;
        float x2 = O[jd][2] * inv1, x3 = O[jd][3] * inv1;
        uint32_t h0 = pack_bf16(x0, x1), h1 = pack_bf16(x2, x3);
        *(uint32_t*)(g_MHhi + base0 + jd * 8)            = h0;
        *(uint32_t*)(g_MHhi + base0 + 8 * 1024 + jd * 8) = h1;
        *(uint32_t*)(g_MHlo + base0 + jd * 8)            = pack_bf16_res(x0, x1, h0);
        *(uint32_t*)(g_MHlo + base0 + 8 * 1024 + jd * 8) = pack_bf16_res(x2, x3, h1);
    }
}

// ---------------------------------------------------------------------------
extern "C" void kernel_launch(void* const* d_in, const int* in_sizes, int n_in,
                              void* d_out, int out_size) {
    const float* q    = (const float*)d_in[0];
    const float* k    = (const float*)d_in[1];
    const float* v    = (const float*)d_in[2];
    const int*   mask = (const int*)  d_in[3];
    const float* Wq   = (const float*)d_in[4];
    const float* Wk   = (const float*)d_in[5];
    const float* Wv   = (const float*)d_in[6];
    const float* Wo   = (const float*)d_in[7];
    float* out = (float*)d_out;

    __nv_bfloat16 *pAh, *pAl, *pWh, *pWl, *pQh, *pQl, *pMh, *pMl;
    cudaGetSymbolAddress((void**)&pAh, g_A3hi);
    cudaGetSymbolAddress((void**)&pAl, g_A3lo);
    cudaGetSymbolAddress((void**)&pWh, g_W4hi);
    cudaGetSymbolAddress((void**)&pWl, g_W4lo);
    cudaGetSymbolAddress((void**)&pQh, g_QKVhi);
    cudaGetSymbolAddress((void**)&pQl, g_QKVlo);
    cudaGetSymbolAddress((void**)&pMh, g_MHhi);
    cudaGetSymbolAddress((void**)&pMl, g_MHlo);

    cudaFuncSetAttribute(gemm_mma,
                         cudaFuncAttributeMaxDynamicSharedMemorySize, GEMM_SMEM);
    cudaFuncSetAttribute(attn_mma,
                         cudaFuncAttributeMaxDynamicSharedMemorySize, ATTN_SMEM);

    dim3 cb(256);
    dim3 csA((NA_ / 4 + 255) / 256, 3);      // q,k,v activations
    dim3 csW((NW_ / 4 + 255) / 256, 4);      // Wq,Wk,Wv,Wo
    dim3 gg3(8, 64, 3);                      // batched Q/K/V projections
    dim3 gg1(8, 64, 1);                      // output projection
    dim3 ga(16, 16, 4);                      // attention

    split_multi<<<csA, cb>>>(q, k, v, v, pAh, pAl, NA_);
    split_multi<<<csW, cb>>>(Wq, Wk, Wv, Wo, pWh, pWl, NW_);
    gemm_mma<<<gg3, 256, GEMM_SMEM>>>(pAh, pAl, pWh, pWl,
                                      nullptr, pQh, pQl, 1);
    attn_mma<<<ga, 256, ATTN_SMEM>>>(mask);
    gemm_mma<<<gg1, 256, GEMM_SMEM>>>(pMh, pMl, pWh + (size_t)3 * NW_,
                                      pWl + (size_t)3 * NW_,
                                      out, nullptr, nullptr, 0);
}

// round 16
// speedup vs baseline: 3.2225x; 1.0076x over previous
#include <cuda_runtime.h>
#include <cuda_bf16.h>
#include <cstdint>

#define B_   4
#define S_   2048
#define DM_  1024
#define H_   16
#define DK_  64
#define NA_  (B_*S_*DM_)      // 8,388,608
#define NW_  (DM_*DM_)        // 1,048,576

// ---------------- scratch (device globals; allocation-free) ----------------
__device__ __nv_bfloat16 g_A3hi[3*NA_];    // split activations q,k,v (z-stacked)
__device__ __nv_bfloat16 g_A3lo[3*NA_];
__device__ __nv_bfloat16 g_W4hi[4*NW_];    // split weights Wq,Wk,Wv,Wo
__device__ __nv_bfloat16 g_W4lo[4*NW_];
__device__ __nv_bfloat16 g_QKVhi[3*NA_];   // projected Q,K,V (z-stacked)
__device__ __nv_bfloat16 g_QKVlo[3*NA_];
__device__ __nv_bfloat16 g_MHhi[NA_];      // merged heads
__device__ __nv_bfloat16 g_MHlo[NA_];

// ---------------- helpers (baseline PTX only: valid at .target sm_103) -----
__device__ __forceinline__ uint32_t smem_u32(const void* p) {
    uint32_t a;
    asm("{ .reg .u64 t; cvta.to.shared.u64 t, %1; cvt.u32.u64 %0, t; }"
        : "=r"(a) : "l"(p));
    return a;
}
__device__ __forceinline__ void ldsm4(uint32_t* r, uint32_t a) {
    asm volatile("ldmatrix.sync.aligned.m8n8.x4.shared.b16 {%0,%1,%2,%3}, [%4];"
                 : "=r"(r[0]), "=r"(r[1]), "=r"(r[2]), "=r"(r[3]) : "r"(a));
}
__device__ __forceinline__ void ldsm4t(uint32_t* r, uint32_t a) {
    asm volatile("ldmatrix.sync.aligned.m8n8.x4.trans.shared.b16 {%0,%1,%2,%3}, [%4];"
                 : "=r"(r[0]), "=r"(r[1]), "=r"(r[2]), "=r"(r[3]) : "r"(a));
}
__device__ __forceinline__ void mma16816(float* d, const uint32_t* a,
                                         const uint32_t* b) {
    asm volatile(
        "mma.sync.aligned.m16n8k16.row.col.f32.bf16.bf16.f32 "
        "{%0,%1,%2,%3}, {%4,%5,%6,%7}, {%8,%9}, {%0,%1,%2,%3};"
        : "+f"(d[0]), "+f"(d[1]), "+f"(d[2]), "+f"(d[3])
        : "r"(a[0]), "r"(a[1]), "r"(a[2]), "r"(a[3]), "r"(b[0]), "r"(b[1]));
}
#define CP16(dst, src) \
    asm volatile("cp.async.cg.shared.global [%0], [%1], 16;" \
                 :: "r"(dst), "l"(src))
#define CPCOMMIT() asm volatile("cp.async.commit_group;" ::: "memory")
#define CPWAIT(n)  asm volatile("cp.async.wait_group %0;" :: "n"(n) : "memory")

// pack two fp32 -> bf16x2 in ONE cvt instruction (lo = x, hi = y)
__device__ __forceinline__ uint32_t pack_bf16(float x, float y) {
    uint32_t r;
    asm("cvt.rn.bf16x2.f32 %0, %1, %2;" : "=r"(r) : "f"(y), "f"(x));
    return r;
}
// residual pair: bf16->fp32 is a 16-bit shift, so unpack is shl/and
__device__ __forceinline__ uint32_t pack_bf16_res(float x, float y,
                                                  uint32_t hi) {
    float hx = __uint_as_float(hi << 16);
    float hy = __uint_as_float(hi & 0xffff0000u);
    return pack_bf16(x - hx, y - hy);
}

// ---------------------------------------------------------------------------
// batched split: slice blockIdx.y of up to 4 fp32 srcs -> bf16 hi/lo at y*n
// ---------------------------------------------------------------------------
__global__ void split_multi(const float* __restrict__ s0,
                            const float* __restrict__ s1,
                            const float* __restrict__ s2,
                            const float* __restrict__ s3,
                            __nv_bfloat16* __restrict__ hi,
                            __nv_bfloat16* __restrict__ lo, int n) {
    const int y = blockIdx.y;
    const float* x = (y == 0) ? s0 : (y == 1) ? s1 : (y == 2) ? s2 : s3;
    int i = (blockIdx.x * blockDim.x + threadIdx.x) * 4;
    if (i >= n) return;
    hi += (size_t)y * n;
    lo += (size_t)y * n;
    float4 v = *(const float4*)(x + i);
    uint32_t h0 = pack_bf16(v.x, v.y), h1 = pack_bf16(v.z, v.w);
    uint32_t l0 = pack_bf16_res(v.x, v.y, h0), l1 = pack_bf16_res(v.z, v.w, h1);
    *(uint32_t*)(hi + i) = h0; *(uint32_t*)(hi + i + 2) = h1;
    *(uint32_t*)(lo + i) = l0; *(uint32_t*)(lo + i + 2) = l1;
}

// ---------------------------------------------------------------------------
// mma.sync bf16x3 GEMM: C[M,1024] = A[M,1024] * W^T, batched over blockIdx.z.
// mode 0: fp32 C.  mode 1: bf16 hi/lo split to Chi/Clo (+z*NA_).
// 128x128 CTA tile, BK=32, single-sync double-buffered cp.async.
// ---------------------------------------------------------------------------
#define BK          32
#define LDSTR       40
#define MAT_ELEMS   (128 * LDSTR)
#define STAGE_ELEMS (4 * MAT_ELEMS)
#define GEMM_SMEM   (2 * STAGE_ELEMS * 2)

__global__ __launch_bounds__(256, 2) void gemm_mma(
    const __nv_bfloat16* __restrict__ Ahi, const __nv_bfloat16* __restrict__ Alo,
    const __nv_bfloat16* __restrict__ Whi, const __nv_bfloat16* __restrict__ Wlo,
    float* __restrict__ C, __nv_bfloat16* __restrict__ Chi,
    __nv_bfloat16* __restrict__ Clo, int mode) {
    extern __shared__ __nv_bfloat16 smem[];
    const uint32_t sbase = smem_u32(smem);

    const int z = blockIdx.z;
    Ahi += (size_t)z * NA_; Alo += (size_t)z * NA_;
    Whi += (size_t)z * NW_; Wlo += (size_t)z * NW_;

    const int tid = threadIdx.x;
    const int wid = tid >> 5;
    const int lid = tid & 31;
    const int wm  = wid >> 1;
    const int wn  = wid & 1;
    const int bm  = blockIdx.y * 128;
    const int bn  = blockIdx.x * 128;

    const int lrow = tid >> 2;
    const int lseg = tid & 3;
    const __nv_bfloat16* gsrc[4];
    gsrc[0] = Ahi + (size_t)(bm + lrow) * 1024 + lseg * 8;
    gsrc[1] = Alo + (size_t)(bm + lrow) * 1024 + lseg * 8;
    gsrc[2] = Whi + (size_t)(bn + lrow) * 1024 + lseg * 8;
    gsrc[3] = Wlo + (size_t)(bn + lrow) * 1024 + lseg * 8;
    const uint32_t sdst = sbase + (uint32_t)(lrow * LDSTR + lseg * 8) * 2;

    const int ra = ((lid >> 3) & 1) * 8 + (lid & 7);
    const int ca = (lid >> 4) * 8;
    const uint32_t aoff = (uint32_t)((wm * 32 + ra) * LDSTR + ca);
    const int rb = (lid >> 4) * 8 + (lid & 7);
    const int cb = ((lid >> 3) & 1) * 8;
    const uint32_t boff = (uint32_t)((wn * 64 + rb) * LDSTR + cb);

    float acc[2][8][4];
#pragma unroll
    for (int t = 0; t < 2; t++)
#pragma unroll
        for (int j = 0; j < 8; j++)
#pragma unroll
            for (int e = 0; e < 4; e++) acc[t][j][e] = 0.f;

    // prologue: stage 0
#pragma unroll
    for (int m = 0; m < 4; m++)
#pragma unroll
        for (int r2 = 0; r2 < 2; r2++)
            CP16(sdst + (uint32_t)(m * MAT_ELEMS + r2 * 64 * LDSTR) * 2,
                 gsrc[m] + (size_t)r2 * 64 * 1024);
    CPCOMMIT();

    for (int kc = 0; kc < 32; ++kc) {
        CPWAIT(0);
        __syncthreads();            // stage kc ready; slot kc^1 free everywhere
        if (kc < 31) {
            const int k0 = (kc + 1) * BK;
            const uint32_t sb2 = sdst + (uint32_t)(((kc + 1) & 1) * STAGE_ELEMS) * 2;
#pragma unroll
            for (int m = 0; m < 4; m++)
#pragma unroll
                for (int r2 = 0; r2 < 2; r2++)
                    CP16(sb2 + (uint32_t)(m * MAT_ELEMS + r2 * 64 * LDSTR) * 2,
                         gsrc[m] + (size_t)r2 * 64 * 1024 + k0);
            CPCOMMIT();
        }

        const uint32_t mb   = sbase + (uint32_t)((kc & 1) * STAGE_ELEMS) * 2;
        const uint32_t bAhi = mb;
        const uint32_t bAlo = mb + MAT_ELEMS * 2;
        const uint32_t bWhi = mb + 2 * MAT_ELEMS * 2;
        const uint32_t bWlo = mb + 3 * MAT_ELEMS * 2;

#pragma unroll
        for (int k16 = 0; k16 < 2; k16++) {
            const uint32_t kadd = (uint32_t)(k16 * 16) * 2;
            uint32_t ah[2][4], al[2][4];
#pragma unroll
            for (int t = 0; t < 2; t++) {
                const uint32_t ao = (aoff + t * 16 * LDSTR) * 2 + kadd;
                ldsm4(ah[t], bAhi + ao);
                ldsm4(al[t], bAlo + ao);
            }
#pragma unroll
            for (int jp = 0; jp < 4; jp++) {
                const uint32_t bo = (boff + jp * 16 * LDSTR) * 2 + kadd;
                uint32_t bh4[4], bl4[4];
                ldsm4(bh4, bWhi + bo);
                ldsm4(bl4, bWlo + bo);
#pragma unroll
                for (int t = 0; t < 2; t++) {
                    mma16816(acc[t][2*jp],   ah[t], bh4);
                    mma16816(acc[t][2*jp],   ah[t], bl4);
                    mma16816(acc[t][2*jp],   al[t], bh4);
                    mma16816(acc[t][2*jp+1], ah[t], bh4 + 2);
                    mma16816(acc[t][2*jp+1], ah[t], bl4 + 2);
                    mma16816(acc[t][2*jp+1], al[t], bh4 + 2);
                }
            }
        }
    }

    const int r0 = bm + wm * 32 + (lid >> 2);
    const int c0 = bn + wn * 64 + (lid & 3) * 2;
    if (mode == 0) {
#pragma unroll
        for (int t = 0; t < 2; t++)
#pragma unroll
            for (int j = 0; j < 8; j++) {
                float* p0 = C + (size_t)(r0 + t * 16) * 1024 + c0 + j * 8;
                float* p1 = p0 + 8 * 1024;
                *(float2*)p0 = make_float2(acc[t][j][0], acc[t][j][1]);
                *(float2*)p1 = make_float2(acc[t][j][2], acc[t][j][3]);
            }
    } else {
        Chi += (size_t)z * NA_; Clo += (size_t)z * NA_;
#pragma unroll
        for (int t = 0; t < 2; t++)
#pragma unroll
            for (int j = 0; j < 8; j++) {
                size_t i0 = (size_t)(r0 + t * 16) * 1024 + c0 + j * 8;
                size_t i1 = i0 + 8 * 1024;
                uint32_t h0 = pack_bf16(acc[t][j][0], acc[t][j][1]);
                uint32_t h1 = pack_bf16(acc[t][j][2], acc[t][j][3]);
                *(uint32_t*)(Chi + i0) = h0;
                *(uint32_t*)(Chi + i1) = h1;
                *(uint32_t*)(Clo + i0) = pack_bf16_res(acc[t][j][0], acc[t][j][1], h0);
                *(uint32_t*)(Clo + i1) = pack_bf16_res(acc[t][j][2], acc[t][j][3], h1);
            }
    }
}

// ---------------------------------------------------------------------------
// Tensor-core flash attention (mma.sync, bf16x3 for QK^T and PV).
// Grid (S/128, H, B), 256 threads = 8 warps x 16 q-rows.
// Key tiles of 64, single-sync double-buffered cp.async K/V hi/lo.
// Mask pre-converted to float bias; warp-uniform O-rescale skip.
// ---------------------------------------------------------------------------
#define ALDS      72
#define KV_MAT    (64 * ALDS)
#define KV_STAGE  (4 * KV_MAT)
#define Q_OFF     (2 * KV_STAGE)
#define Q_MAT     (128 * ALDS)
#define MSK_OFF   ((Q_OFF + 2 * Q_MAT) * 2)
#define ATTN_SMEM (MSK_OFF + 2 * 64 * 4)
#define LOG2E     1.4426950408889634f

__global__ __launch_bounds__(256, 2) void attn_mma(const int* __restrict__ mask) {
    extern __shared__ __nv_bfloat16 sm[];
    const uint32_t sb = smem_u32(sm);
    float* mskb = (float*)((char*)sm + MSK_OFF);   // 0 or -1e9 per key

    const int b   = blockIdx.z;
    const int h   = blockIdx.y;
    const int q0  = blockIdx.x * 128;
    const int tid = threadIdx.x;
    const int w   = tid >> 5;
    const int lid = tid & 31;

    const size_t rowb = (size_t)b * 2048;
    const __nv_bfloat16* Qh = g_QKVhi + (rowb + q0) * 1024 + h * 64;
    const __nv_bfloat16* Ql = g_QKVlo + (rowb + q0) * 1024 + h * 64;
    const __nv_bfloat16* Kh = g_QKVhi + (size_t)NA_ + rowb * 1024 + h * 64;
    const __nv_bfloat16* Kl = g_QKVlo + (size_t)NA_ + rowb * 1024 + h * 64;
    const __nv_bfloat16* Vh = g_QKVhi + (size_t)2 * NA_ + rowb * 1024 + h * 64;
    const __nv_bfloat16* Vl = g_QKVlo + (size_t)2 * NA_ + rowb * 1024 + h * 64;

    // ---- prologue: Q (hi/lo) + KV stage0 + mask0 ----
    {
        const int qrow = tid >> 1;
        const int qs0  = (tid & 1) * 4;
#pragma unroll
        for (int i = 0; i < 4; i++) {
            int seg = qs0 + i;
            CP16(sb + (uint32_t)(Q_OFF + qrow * ALDS + seg * 8) * 2,
                 Qh + (size_t)qrow * 1024 + seg * 8);
            CP16(sb + (uint32_t)(Q_OFF + Q_MAT + qrow * ALDS + seg * 8) * 2,
                 Ql + (size_t)qrow * 1024 + seg * 8);
        }
        const int krow = tid >> 2;
        const int ks0  = (tid & 3) * 2;
#pragma unroll
        for (int e = 0; e < 2; e++) {
            int seg = ks0 + e;
            uint32_t d0 = sb + (uint32_t)(krow * ALDS + seg * 8) * 2;
            const size_t g = (size_t)krow * 1024 + seg * 8;
            CP16(d0,                  Kh + g);
            CP16(d0 + KV_MAT * 2,     Kl + g);
            CP16(d0 + 2 * KV_MAT * 2, Vh + g);
            CP16(d0 + 3 * KV_MAT * 2, Vl + g);
        }
        if (tid < 64) mskb[tid] = (mask[b * 2048 + tid] == 0) ? -1e9f : 0.f;
        CPCOMMIT();
        CPWAIT(0);
        __syncthreads();
    }

    const int ra = ((lid >> 3) & 1) * 8 + (lid & 7);
    const int ca = (lid >> 4) * 8;
    const uint32_t qbase = sb + (uint32_t)(Q_OFF + (w * 16 + ra) * ALDS + ca) * 2;

    float O[8][4];
#pragma unroll
    for (int j = 0; j < 8; j++)
#pragma unroll
        for (int e = 0; e < 4; e++) O[j][e] = 0.f;
    float m0 = -1e30f, m1 = -1e30f, l0 = 0.f, l1 = 0.f;

    const int rbB = (lid >> 4) * 8 + (lid & 7);
    const int cbB = ((lid >> 3) & 1) * 8;
    const int cb2 = (lid & 3) * 2;

    for (int kc = 0; kc < 32; kc++) {
        CPWAIT(0);
        __syncthreads();
        if (kc < 31) {
            const int k0 = (kc + 1) * 64;
            const uint32_t st2 = sb + (uint32_t)(((kc + 1) & 1) * KV_STAGE) * 2;
            const int krow = tid >> 2;
            const int ks0  = (tid & 3) * 2;
#pragma unroll
            for (int e = 0; e < 2; e++) {
                int seg = ks0 + e;
                uint32_t d0 = st2 + (uint32_t)(krow * ALDS + seg * 8) * 2;
                const size_t g = (size_t)(k0 + krow) * 1024 + seg * 8;
                CP16(d0,                  Kh + g);
                CP16(d0 + KV_MAT * 2,     Kl + g);
                CP16(d0 + 2 * KV_MAT * 2, Vh + g);
                CP16(d0 + 3 * KV_MAT * 2, Vl + g);
            }
            if (tid < 64)
                mskb[((kc + 1) & 1) * 64 + tid] =
                    (mask[b * 2048 + k0 + tid] == 0) ? -1e9f : 0.f;
            CPCOMMIT();
        }

        const uint32_t st = sb + (uint32_t)((kc & 1) * KV_STAGE) * 2;

        // ---- S = Q K^T (3-term); Q fragments reloaded from smem ----
        float sC[8][4];
#pragma unroll
        for (int j = 0; j < 8; j++)
#pragma unroll
            for (int e = 0; e < 4; e++) sC[j][e] = 0.f;
#pragma unroll
        for (int t = 0; t < 4; t++) {
            uint32_t qh4[4], ql4[4];
            ldsm4(qh4, qbase + (uint32_t)(t * 16) * 2);
            ldsm4(ql4, qbase + (uint32_t)(Q_MAT + t * 16) * 2);
#pragma unroll
            for (int np = 0; np < 4; np++) {
                uint32_t bo = st + (uint32_t)((np * 16 + rbB) * ALDS + t * 16 + cbB) * 2;
                uint32_t kh4[4], kl4[4];
                ldsm4(kh4, bo);
                ldsm4(kl4, bo + KV_MAT * 2);
                mma16816(sC[2*np],   qh4, kh4);
                mma16816(sC[2*np],   qh4, kl4);
                mma16816(sC[2*np],   ql4, kh4);
                mma16816(sC[2*np+1], qh4, kh4 + 2);
                mma16816(sC[2*np+1], qh4, kl4 + 2);
                mma16816(sC[2*np+1], ql4, kh4 + 2);
            }
        }

        // ---- bias-mask + scale (fmaf) + online softmax (base-2) ----
        const float* mkc = mskb + (kc & 1) * 64;
        const float sc2 = 0.125f * LOG2E;
        float rmax0 = -1e30f, rmax1 = -1e30f;
#pragma unroll
        for (int j = 0; j < 8; j++) {
            float b0 = mkc[j * 8 + cb2];
            float b1 = mkc[j * 8 + cb2 + 1];
            sC[j][0] = fmaf(sC[j][0], sc2, b0);
            sC[j][1] = fmaf(sC[j][1], sc2, b1);
            sC[j][2] = fmaf(sC[j][2], sc2, b0);
            sC[j][3] = fmaf(sC[j][3], sc2, b1);
            rmax0 = fmaxf(rmax0, fmaxf(sC[j][0], sC[j][1]));
            rmax1 = fmaxf(rmax1, fmaxf(sC[j][2], sC[j][3]));
        }
        rmax0 = fmaxf(rmax0, __shfl_xor_sync(0xffffffffu, rmax0, 1));
        rmax0 = fmaxf(rmax0, __shfl_xor_sync(0xffffffffu, rmax0, 2));
        rmax1 = fmaxf(rmax1, __shfl_xor_sync(0xffffffffu, rmax1, 1));
        rmax1 = fmaxf(rmax1, __shfl_xor_sync(0xffffffffu, rmax1, 2));

        const float mn0 = fmaxf(m0, rmax0), mn1 = fmaxf(m1, rmax1);
        const bool nochg = __all_sync(0xffffffffu, (mn0 == m0) & (mn1 == m1));
        float rs0 = 0.f, rs1 = 0.f;
#pragma unroll
        for (int j = 0; j < 8; j++) {
            sC[j][0] = exp2f(sC[j][0] - mn0);
            sC[j][1] = exp2f(sC[j][1] - mn0);
            sC[j][2] = exp2f(sC[j][2] - mn1);
            sC[j][3] = exp2f(sC[j][3] - mn1);
            rs0 += sC[j][0] + sC[j][1];
            rs1 += sC[j][2] + sC[j][3];
        }
        rs0 += __shfl_xor_sync(0xffffffffu, rs0, 1);
        rs0 += __shfl_xor_sync(0xffffffffu, rs0, 2);
        rs1 += __shfl_xor_sync(0xffffffffu, rs1, 1);
        rs1 += __shfl_xor_sync(0xffffffffu, rs1, 2);

        if (nochg) {                     // warp-uniform: no rescale needed
            l0 += rs0;
            l1 += rs1;
        } else {
            const float corr0 = exp2f(m0 - mn0), corr1 = exp2f(m1 - mn1);
            m0 = mn0; m1 = mn1;
            l0 = l0 * corr0 + rs0;
            l1 = l1 * corr1 + rs1;
#pragma unroll
            for (int j = 0; j < 8; j++) {
                O[j][0] *= corr0; O[j][1] *= corr0;
                O[j][2] *= corr1; O[j][3] *= corr1;
            }
        }

        // ---- O += P V (3-term); P packed straight from sC registers ----
#pragma unroll
        for (int t = 0; t < 4; t++) {
            uint32_t ph[4], pl[4];
            ph[0] = pack_bf16(sC[2*t][0],   sC[2*t][1]);
            ph[1] = pack_bf16(sC[2*t][2],   sC[2*t][3]);
            ph[2] = pack_bf16(sC[2*t+1][0], sC[2*t+1][1]);
            ph[3] = pack_bf16(sC[2*t+1][2], sC[2*t+1][3]);
            pl[0] = pack_bf16_res(sC[2*t][0],   sC[2*t][1],   ph[0]);
            pl[1] = pack_bf16_res(sC[2*t][2],   sC[2*t][3],   ph[1]);
            pl[2] = pack_bf16_res(sC[2*t+1][0], sC[2*t+1][1], ph[2]);
            pl[3] = pack_bf16_res(sC[2*t+1][2], sC[2*t+1][3], ph[3]);

#pragma unroll
            for (int dp = 0; dp < 4; dp++) {
                uint32_t vo = st + (uint32_t)(2 * KV_MAT) * 2 +
                              (uint32_t)((t * 16 + ra) * ALDS + dp * 16 + ca) * 2;
                uint32_t vh4[4], vl4[4];
                ldsm4t(vh4, vo);
                ldsm4t(vl4, vo + KV_MAT * 2);
                mma16816(O[2*dp],   ph, vh4);
                mma16816(O[2*dp],   ph, vl4);
                mma16816(O[2*dp],   pl, vh4);
                mma16816(O[2*dp+1], ph, vh4 + 2);
                mma16816(O[2*dp+1], ph, vl4 + 2);
                mma16816(O[2*dp+1], pl, vh4 + 2);
            }
        }
    }

    // ---- epilogue: O/l -> MH hi/lo bf16 ----
    const float inv0 = 1.f / l0, inv1 = 1.f / l1;
    const int row0 = q0 + w * 16 + (lid >> 2);
    const size_t base0 = (rowb + row0) * 1024 + h * 64 + cb2;
#pragma unroll
    for (int jd = 0; jd < 8; jd++) {
        float x0 = O[jd][0] * inv0, x1 = O[jd][1] * inv0;
        float x2 = O[jd][2] * inv1, x3 = O[jd][3] * inv1;
        uint32_t h0 = pack_bf16(x0, x1), h1 = pack_bf16(x2, x3);
        *(uint32_t*)(g_MHhi + base0 + jd * 8)            = h0;
        *(uint32_t*)(g_MHhi + base0 + 8 * 1024 + jd * 8) = h1;
        *(uint32_t*)(g_MHlo + base0 + jd * 8)            = pack_bf16_res(x0, x1, h0);
        *(uint32_t*)(g_MHlo + base0 + 8 * 1024 + jd * 8) = pack_bf16_res(x2, x3, h1);
    }
}

// ---------------------------------------------------------------------------
extern "C" void kernel_launch(void* const* d_in, const int* in_sizes, int n_in,
                              void* d_out, int out_size) {
    const float* q    = (const float*)d_in[0];
    const float* k    = (const float*)d_in[1];
    const float* v    = (const float*)d_in[2];
    const int*   mask = (const int*)  d_in[3];
    const float* Wq   = (const float*)d_in[4];
    const float* Wk   = (const float*)d_in[5];
    const float* Wv   = (const float*)d_in[6];
    const float* Wo   = (const float*)d_in[7];
    float* out = (float*)d_out;

    __nv_bfloat16 *pAh, *pAl, *pWh, *pWl, *pQh, *pQl, *pMh, *pMl;
    cudaGetSymbolAddress((void**)&pAh, g_A3hi);
    cudaGetSymbolAddress((void**)&pAl, g_A3lo);
    cudaGetSymbolAddress((void**)&pWh, g_W4hi);
    cudaGetSymbolAddress((void**)&pWl, g_W4lo);
    cudaGetSymbolAddress((void**)&pQh, g_QKVhi);
    cudaGetSymbolAddress((void**)&pQl, g_QKVlo);
    cudaGetSymbolAddress((void**)&pMh, g_MHhi);
    cudaGetSymbolAddress((void**)&pMl, g_MHlo);

    cudaFuncSetAttribute(gemm_mma,
                         cudaFuncAttributeMaxDynamicSharedMemorySize, GEMM_SMEM);
    cudaFuncSetAttribute(attn_mma,
                         cudaFuncAttributeMaxDynamicSharedMemorySize, ATTN_SMEM);

    dim3 cb(256);
    dim3 csA((NA_ / 4 + 255) / 256, 3);      // q,k,v activations
    dim3 csW((NW_ / 4 + 255) / 256, 4);      // Wq,Wk,Wv,Wo
    dim3 gg3(8, 64, 3);                      // batched Q/K/V projections
    dim3 gg1(8, 64, 1);                      // output projection
    dim3 ga(16, 16, 4);                      // attention

    split_multi<<<csA, cb>>>(q, k, v, v, pAh, pAl, NA_);
    split_multi<<<csW, cb>>>(Wq, Wk, Wv, Wo, pWh, pWl, NW_);
    gemm_mma<<<gg3, 256, GEMM_SMEM>>>(pAh, pAl, pWh, pWl,
                                      nullptr, pQh, pQl, 1);
    attn_mma<<<ga, 256, ATTN_SMEM>>>(mask);
    gemm_mma<<<gg1, 256, GEMM_SMEM>>>(pMh, pMl, pWh + (size_t)3 * NW_,
                                      pWl + (size_t)3 * NW_,
                                      out, nullptr, nullptr, 0);
}